// round 9
// baseline (speedup 1.0000x reference)
#include <cuda_runtime.h>
#include <math.h>

// Problem constants (fixed by setup_inputs)
#define HW    65536          // 256*256
#define WIMG  256
#define CC    256
#define BB    2
#define NHH   16
#define DHH   16
#define TP    257            // pooled plane dim (H+1)
#define TPL   (TP*TP)

#define QSCALE 0.3606737602222409f    // 0.25 * log2(e)
#define LOG2E  1.4426950408889634f

// ---------------- scratch (device globals; no allocs allowed) ----------------
static __device__ float g_q [BB*CC*HW];
static __device__ float g_k [BB*CC*HW];
static __device__ float g_v1[BB*CC*HW];
static __device__ float g_v2[BB*CC*HW];
static __device__ float g_o [BB*CC*HW];
static __device__ float g_t [BB*CC*TPL];
static __device__ float g_u [BB*CC*HW];
static __device__ float g_pwf[CC*CC];
static __device__ float g_pwb[CC];
static __device__ float g_biasf[NHH*4*8*128*4];   // bias in mma C-fragment layout

// ---------------- prep: fold BN into pointwise weights ----------------
__global__ void prep_kernel(const float* __restrict__ pw,
                            const float* __restrict__ gamma,
                            const float* __restrict__ beta,
                            const float* __restrict__ mean,
                            const float* __restrict__ var)
{
    __shared__ float red[256];
    int o = blockIdx.x, c = threadIdx.x;
    float inv = gamma[c] * rsqrtf(var[c] + 1e-5f);
    float w = pw[o*CC + c];
    g_pwf[o*CC + c] = w * inv;
    red[c] = w * (beta[c] - mean[c]*inv);
    __syncthreads();
    for (int s = 128; s > 0; s >>= 1) {
        if (c < s) red[c] += red[c+s];
        __syncthreads();
    }
    if (c == 0) g_pwb[o] = red[0];
}

// ---------------- bias prep: rel-pos bias in mma C-fragment layout, x log2e ----
__global__ void bias_prep(const float* __restrict__ rel_bias)
{
    int h = blockIdx.x, mi = blockIdx.y, ni = blockIdx.z;
    int lane = threadIdx.x;
    int g = lane >> 2, t = lane & 3;
    float v[4];
    #pragma unroll
    for (int rr = 0; rr < 2; rr++) {
        int i = mi*16 + g + rr*8;
        #pragma unroll
        for (int cc = 0; cc < 2; cc++) {
            int j = ni*8 + 2*t + cc;
            int idx = ((i>>3) - (j>>3) + 7)*15 + ((i&7) - (j&7) + 7);
            v[rr*2 + cc] = LOG2E * rel_bias[idx*NHH + h];
        }
    }
    *(float4*)&g_biasf[(((h*4 + mi)*8 + ni)*128 + lane*4)] =
        make_float4(v[0], v[1], v[2], v[3]);
}

// ---------------- tf32 helpers ----------------
__device__ __forceinline__ unsigned f2tf(float x) {
    unsigned r; asm("cvt.rna.tf32.f32 %0, %1;" : "=r"(r) : "f"(x)); return r;
}
__device__ __forceinline__ float ex2(float x) {
    float r; asm("ex2.approx.ftz.f32 %0, %1;" : "=f"(r) : "f"(x)); return r;
}
__device__ __forceinline__ void mma8(float* c, const unsigned* a, const unsigned* b) {
    asm volatile(
        "mma.sync.aligned.m16n8k8.row.col.f32.tf32.tf32.f32 "
        "{%0,%1,%2,%3},{%4,%5,%6,%7},{%8,%9},{%0,%1,%2,%3};"
        : "+f"(c[0]), "+f"(c[1]), "+f"(c[2]), "+f"(c[3])
        : "r"(a[0]), "r"(a[1]), "r"(a[2]), "r"(a[3]), "r"(b[0]), "r"(b[1]));
}

// ---------------- core tf32 GEMM: 128(M) x 256(N) block tile, K=256 -----------
// 8 warps (2m x 4n), warp tile 64x64, BK=8, double-buffered smem.
#define ASTR 136
#define BSTR 264

__device__ __forceinline__ void gemm_big_tf32(
    const float* __restrict__ wb,    // [128, 256] row-major weights
    const float* __restrict__ xb,    // [256, HW] activations
    float* __restrict__ ob,          // output base
    int n0,
    const float* __restrict__ bias)
{
    __shared__ __align__(16) unsigned As[2][8*ASTR];
    __shared__ __align__(16) unsigned Bs[2][8*BSTR];

    int tid  = threadIdx.x;
    int lane = tid & 31, warp = tid >> 5;
    int wm = warp >> 2, wn = warp & 3;
    int gid = lane >> 2, tig = lane & 3;

    int arow = tid >> 1;                  // A loader: 128 rows x 8 k
    int akq  = (tid & 1) * 4;
    int brow = tid >> 5;                  // B loader: 8 rows, warp per row
    int bcol = lane * 4;

    float acc[4][8][4];
    #pragma unroll
    for (int mt = 0; mt < 4; mt++)
        #pragma unroll
        for (int nt = 0; nt < 8; nt++)
            #pragma unroll
            for (int i = 0; i < 4; i++) acc[mt][nt][i] = 0.f;

    // prologue: load + store k-block 0 into buffer 0
    float4 ap = *(const float4*)(wb + (size_t)arow*CC + akq);
    float4 bp0 = *(const float4*)(xb + (size_t)brow*HW + n0 + bcol);
    float4 bp1 = *(const float4*)(xb + (size_t)brow*HW + n0 + bcol + 128);
    As[0][(akq+0)*ASTR + arow] = f2tf(ap.x);
    As[0][(akq+1)*ASTR + arow] = f2tf(ap.y);
    As[0][(akq+2)*ASTR + arow] = f2tf(ap.z);
    As[0][(akq+3)*ASTR + arow] = f2tf(ap.w);
    *(uint4*)&Bs[0][brow*BSTR + bcol] =
        make_uint4(f2tf(bp0.x), f2tf(bp0.y), f2tf(bp0.z), f2tf(bp0.w));
    *(uint4*)&Bs[0][brow*BSTR + bcol + 128] =
        make_uint4(f2tf(bp1.x), f2tf(bp1.y), f2tf(bp1.z), f2tf(bp1.w));
    __syncthreads();

    #pragma unroll 4
    for (int it = 0; it < 32; it++) {
        int p = it & 1;
        if (it < 31) {
            int k0 = (it + 1) * 8;
            ap  = *(const float4*)(wb + (size_t)arow*CC + k0 + akq);
            bp0 = *(const float4*)(xb + (size_t)(k0 + brow)*HW + n0 + bcol);
            bp1 = *(const float4*)(xb + (size_t)(k0 + brow)*HW + n0 + bcol + 128);
        }

        unsigned af[4][4], bf[8][2];
        #pragma unroll
        for (int mt = 0; mt < 4; mt++) {
            int m = wm*64 + mt*16 + gid;
            af[mt][0] = As[p][(tig  )*ASTR + m];
            af[mt][1] = As[p][(tig  )*ASTR + m + 8];
            af[mt][2] = As[p][(tig+4)*ASTR + m];
            af[mt][3] = As[p][(tig+4)*ASTR + m + 8];
        }
        #pragma unroll
        for (int nt = 0; nt < 8; nt++) {
            int n = wn*64 + nt*8 + gid;
            bf[nt][0] = Bs[p][(tig  )*BSTR + n];
            bf[nt][1] = Bs[p][(tig+4)*BSTR + n];
        }
        #pragma unroll
        for (int mt = 0; mt < 4; mt++)
            #pragma unroll
            for (int nt = 0; nt < 8; nt++)
                mma8(acc[mt][nt], af[mt], bf[nt]);

        if (it < 31) {
            int q = p ^ 1;
            As[q][(akq+0)*ASTR + arow] = f2tf(ap.x);
            As[q][(akq+1)*ASTR + arow] = f2tf(ap.y);
            As[q][(akq+2)*ASTR + arow] = f2tf(ap.z);
            As[q][(akq+3)*ASTR + arow] = f2tf(ap.w);
            *(uint4*)&Bs[q][brow*BSTR + bcol] =
                make_uint4(f2tf(bp0.x), f2tf(bp0.y), f2tf(bp0.z), f2tf(bp0.w));
            *(uint4*)&Bs[q][brow*BSTR + bcol + 128] =
                make_uint4(f2tf(bp1.x), f2tf(bp1.y), f2tf(bp1.z), f2tf(bp1.w));
        }
        __syncthreads();
    }

    #pragma unroll
    for (int mt = 0; mt < 4; mt++) {
        int r0 = wm*64 + mt*16 + gid;
        float bia0 = bias ? bias[r0]     : 0.f;
        float bia1 = bias ? bias[r0 + 8] : 0.f;
        #pragma unroll
        for (int nt = 0; nt < 8; nt++) {
            int c = n0 + wn*64 + nt*8 + 2*tig;
            *(float2*)(ob + (size_t)r0*HW + c) =
                make_float2(acc[mt][nt][0] + bia0, acc[mt][nt][1] + bia0);
            *(float2*)(ob + (size_t)(r0+8)*HW + c) =
                make_float2(acc[mt][nt][2] + bia1, acc[mt][nt][3] + bia1);
        }
    }
}

// ---------------- qkv GEMM (both inputs in one launch) ----------------
// z = which*2 + b. which=0: x1 -> q (W rows 0..255), v1; which=1: x2 -> k, v2.
__global__ void __launch_bounds__(256) qkv_gemm(const float* __restrict__ x1,
                                                const float* __restrict__ x2,
                                                const float* __restrict__ Wq)
{
    int z = blockIdx.z;
    int which = z >> 1, b = z & 1;
    int by = blockIdx.y;
    int n0 = blockIdx.x * 256;
    const float* X = which ? x2 : x1;
    float* outA = which ? g_k  : g_q;
    float* outB = which ? g_v2 : g_v1;
    int wrowA   = which ? 256 : 0;
    const float* wb;
    float* ob;
    if (by < 2) { wb = Wq + (size_t)(wrowA + by*128)*CC;
                  ob = outA + (size_t)b*CC*HW + (size_t)(by*128)*HW; }
    else        { wb = Wq + (size_t)(512 + (by-2)*128)*CC;
                  ob = outB + (size_t)b*CC*HW + (size_t)((by-2)*128)*HW; }
    const float* xb = X + (size_t)b*CC*HW;
    gemm_big_tf32(wb, xb, ob, n0, nullptr);
}

// ---------------- pointwise GEMM (BN folded, tf32) ----------------
__global__ void __launch_bounds__(256) pw_gemm(float* __restrict__ out)
{
    int b  = blockIdx.z;
    int by = blockIdx.y;
    int n0 = blockIdx.x * 256;
    const float* wb = g_pwf + (size_t)(by*128)*CC;
    const float* xb = g_u + (size_t)b*CC*HW;
    float* ob = out + (size_t)b*CC*HW + (size_t)(by*128)*HW;
    gemm_big_tf32(wb, xb, ob, n0, g_pwb + by*128);
}

// ---------------- window attention: tensor-core (mma tf32) ----------------
#define TS 72
#define HSZ (16*TS)

__global__ void __launch_bounds__(128) attn_kernel()
{
    int wid = blockIdx.x;                 // 0..2047
    int hp  = blockIdx.y;                 // head pair 0..7
    int b   = wid >> 10;
    int wy  = (wid >> 5) & 31;
    int wx  = wid & 31;
    int tid = threadIdx.x;
    int lane = tid & 31, warp = tid >> 5;
    int hh    = warp >> 1;
    int mbase = (warp & 1) * 32;
    int g = lane >> 2, t = lane & 3;

    __shared__ float sq [2*HSZ];
    __shared__ float sk [2*HSZ];
    __shared__ float svd[2*HSZ];
    __shared__ float svs[2*16];

    if (tid < 32) svs[tid] = 0.f;
    __syncthreads();

    for (int e = tid; e < 2048; e += 128) {
        int lh = e >> 10;
        int r  = e & 1023;
        int dd = r >> 6, tk = r & 63;
        size_t ga = ((size_t)b*CC + (hp*2+lh)*DHH + dd)*HW
                  + (size_t)(wy*8 + (tk>>3))*WIMG + wx*8 + (tk&7);
        sq[lh*HSZ + dd*TS + tk] = g_q[ga] * QSCALE;
        sk[lh*HSZ + dd*TS + tk] = g_k[ga];
        float v1 = g_v1[ga], v2 = g_v2[ga];
        svd[lh*HSZ + dd*TS + tk] = 0.5f*(v1 - v2);
        float s = 0.5f*v2;
        #pragma unroll
        for (int o = 16; o > 0; o >>= 1) s += __shfl_xor_sync(0xffffffffu, s, o);
        if (lane == 0) atomicAdd(&svs[lh*16 + dd], s);
    }
    __syncthreads();

    const float* qh = sq  + hh*HSZ;
    const float* kh = sk  + hh*HSZ;
    const float* vh = svd + hh*HSZ;
    int hgl = hp*2 + hh;

    unsigned aq[2][2][4];
    #pragma unroll
    for (int mi = 0; mi < 2; mi++) {
        int r0 = mbase + mi*16 + g;
        #pragma unroll
        for (int kc = 0; kc < 2; kc++) {
            aq[mi][kc][0] = f2tf(qh[(kc*8+t  )*TS + r0]);
            aq[mi][kc][1] = f2tf(qh[(kc*8+t  )*TS + r0+8]);
            aq[mi][kc][2] = f2tf(qh[(kc*8+t+4)*TS + r0]);
            aq[mi][kc][3] = f2tf(qh[(kc*8+t+4)*TS + r0+8]);
        }
    }

    float acc[2][8][4];
    #pragma unroll
    for (int mi = 0; mi < 2; mi++) {
        int mtg = (warp & 1)*2 + mi;
        #pragma unroll
        for (int ni = 0; ni < 8; ni++) {
            float4 bv = *(const float4*)&g_biasf[(((hgl*4 + mtg)*8 + ni)*128 + lane*4)];
            acc[mi][ni][0] = bv.x; acc[mi][ni][1] = bv.y;
            acc[mi][ni][2] = bv.z; acc[mi][ni][3] = bv.w;
        }
    }

    #pragma unroll
    for (int ni = 0; ni < 8; ni++) {
        unsigned bk[2][2];
        #pragma unroll
        for (int kc = 0; kc < 2; kc++) {
            bk[kc][0] = f2tf(kh[(kc*8+t  )*TS + ni*8 + g]);
            bk[kc][1] = f2tf(kh[(kc*8+t+4)*TS + ni*8 + g]);
        }
        #pragma unroll
        for (int mi = 0; mi < 2; mi++)
            #pragma unroll
            for (int kc = 0; kc < 2; kc++)
                mma8(acc[mi][ni], aq[mi][kc], bk[kc]);
    }

    #pragma unroll
    for (int mi = 0; mi < 2; mi++) {
        float m0 = -1e30f, m1 = -1e30f;
        #pragma unroll
        for (int ni = 0; ni < 8; ni++) {
            m0 = fmaxf(m0, fmaxf(acc[mi][ni][0], acc[mi][ni][1]));
            m1 = fmaxf(m1, fmaxf(acc[mi][ni][2], acc[mi][ni][3]));
        }
        m0 = fmaxf(m0, __shfl_xor_sync(0xffffffffu, m0, 1));
        m0 = fmaxf(m0, __shfl_xor_sync(0xffffffffu, m0, 2));
        m1 = fmaxf(m1, __shfl_xor_sync(0xffffffffu, m1, 1));
        m1 = fmaxf(m1, __shfl_xor_sync(0xffffffffu, m1, 2));
        float s0 = 0.f, s1 = 0.f;
        #pragma unroll
        for (int ni = 0; ni < 8; ni++) {
            float p0 = ex2(acc[mi][ni][0] - m0);
            float p1 = ex2(acc[mi][ni][1] - m0);
            float p2 = ex2(acc[mi][ni][2] - m1);
            float p3 = ex2(acc[mi][ni][3] - m1);
            acc[mi][ni][0] = p0; acc[mi][ni][1] = p1;
            acc[mi][ni][2] = p2; acc[mi][ni][3] = p3;
            s0 += p0 + p1; s1 += p2 + p3;
        }
        s0 += __shfl_xor_sync(0xffffffffu, s0, 1);
        s0 += __shfl_xor_sync(0xffffffffu, s0, 2);
        s1 += __shfl_xor_sync(0xffffffffu, s1, 1);
        s1 += __shfl_xor_sync(0xffffffffu, s1, 2);
        float i0 = 1.0f / s0, i1 = 1.0f / s1;
        #pragma unroll
        for (int ni = 0; ni < 8; ni++) {
            acc[mi][ni][0] = __uint_as_float(f2tf(acc[mi][ni][0]*i0));
            acc[mi][ni][1] = __uint_as_float(f2tf(acc[mi][ni][1]*i0));
            acc[mi][ni][2] = __uint_as_float(f2tf(acc[mi][ni][2]*i1));
            acc[mi][ni][3] = __uint_as_float(f2tf(acc[mi][ni][3]*i1));
        }
    }

    float av[2][2][4];
    #pragma unroll
    for (int mi = 0; mi < 2; mi++)
        #pragma unroll
        for (int no = 0; no < 2; no++) {
            float c0 = svs[hh*16 + no*8 + 2*t];
            float c1 = svs[hh*16 + no*8 + 2*t + 1];
            av[mi][no][0] = c0; av[mi][no][1] = c1;
            av[mi][no][2] = c0; av[mi][no][3] = c1;
        }

    int src0 = (g << 2) | (t >> 1);
    int src1 = src0 + 2;
    bool odd = (t & 1);
    #pragma unroll
    for (int kc2 = 0; kc2 < 8; kc2++) {
        unsigned pa[2][4];
        #pragma unroll
        for (int mi = 0; mi < 2; mi++) {
            float r0 = acc[mi][kc2][0], r1 = acc[mi][kc2][1];
            float r2 = acc[mi][kc2][2], r3 = acc[mi][kc2][3];
            float x00 = __shfl_sync(0xffffffffu, r0, src0);
            float x01 = __shfl_sync(0xffffffffu, r1, src0);
            float x02 = __shfl_sync(0xffffffffu, r2, src0);
            float x03 = __shfl_sync(0xffffffffu, r3, src0);
            float x10 = __shfl_sync(0xffffffffu, r0, src1);
            float x11 = __shfl_sync(0xffffffffu, r1, src1);
            float x12 = __shfl_sync(0xffffffffu, r2, src1);
            float x13 = __shfl_sync(0xffffffffu, r3, src1);
            pa[mi][0] = __float_as_uint(odd ? x01 : x00);
            pa[mi][1] = __float_as_uint(odd ? x03 : x02);
            pa[mi][2] = __float_as_uint(odd ? x11 : x10);
            pa[mi][3] = __float_as_uint(odd ? x13 : x12);
        }
        unsigned bv[2][2];
        #pragma unroll
        for (int no = 0; no < 2; no++) {
            bv[no][0] = f2tf(vh[(no*8+g)*TS + kc2*8 + t]);
            bv[no][1] = f2tf(vh[(no*8+g)*TS + kc2*8 + t + 4]);
        }
        #pragma unroll
        for (int mi = 0; mi < 2; mi++)
            #pragma unroll
            for (int no = 0; no < 2; no++)
                mma8(av[mi][no], pa[mi], bv[no]);
    }

    size_t hb = ((size_t)b*CC + hgl*DHH)*HW + (size_t)(wy*8)*WIMG + wx*8;
    #pragma unroll
    for (int mi = 0; mi < 2; mi++) {
        int r0 = mbase + mi*16 + g;
        int r1 = r0 + 8;
        #pragma unroll
        for (int no = 0; no < 2; no++) {
            int d0 = no*8 + 2*t;
            g_o[hb + (size_t)(d0  )*HW + (r0>>3)*WIMG + (r0&7)] = av[mi][no][0];
            g_o[hb + (size_t)(d0+1)*HW + (r0>>3)*WIMG + (r0&7)] = av[mi][no][1];
            g_o[hb + (size_t)(d0  )*HW + (r1>>3)*WIMG + (r1&7)] = av[mi][no][2];
            g_o[hb + (size_t)(d0+1)*HW + (r1>>3)*WIMG + (r1&7)] = av[mi][no][3];
        }
    }
}

// ---------------- directional avg pools + pad_out ----------------
__global__ void pool_kernel()
{
    int p = blockIdx.x*256 + threadIdx.x;
    if (p >= TPL) return;
    int c = blockIdx.y, b = blockIdx.z;
    int y = p / TP, x = p - y*TP;
    const float* ob = g_o + ((size_t)b*CC + c)*HW;
    float val = 0.f;
    if (y < 256 && x < 256) {
        float sx = 0.f, sy = 0.f;
        #pragma unroll
        for (int t = 0; t < 8; t++) {
            int r = y - 3 + t;
            if (r >= 0 && r <= 256) sx += ob[(r == 256 ? 254 : r)*WIMG + x];
            int cl = x - 3 + t;
            if (cl >= 0 && cl <= 256) sy += ob[y*WIMG + (cl == 256 ? 254 : cl)];
        }
        val = (sx + sy)*0.125f;
    }
    g_t[((size_t)b*CC + c)*TPL + p] = val;
}

// ---------------- depthwise 8x8 conv (pad 3) over t[257x257] -> u[256x256] ----
__global__ void __launch_bounds__(256) dw_kernel(const float* __restrict__ dw)
{
    __shared__ float st[39][41];
    __shared__ float sdw[64];
    int bc = blockIdx.z;
    int y0 = blockIdx.y*32, x0 = blockIdx.x*32;
    const float* tb = g_t + (size_t)bc*TPL;
    int tid = threadIdx.x;
    if (tid < 64) sdw[tid] = dw[(bc & 255)*64 + tid];
    for (int idx = tid; idx < 39*39; idx += 256) {
        int r = idx / 39, cl = idx - r*39;
        int gy = y0 - 3 + r, gx = x0 - 3 + cl;
        float v = 0.f;
        if (gy >= 0 && gy < TP && gx >= 0 && gx < TP) v = tb[gy*TP + gx];
        st[r][cl] = v;
    }
    __syncthreads();
    int oy = tid >> 3, ox = (tid & 7)*4;
    float a0 = 0.f, a1 = 0.f, a2 = 0.f, a3 = 0.f;
    #pragma unroll
    for (int ky = 0; ky < 8; ky++) {
        const float* row = &st[oy+ky][ox];
        #pragma unroll
        for (int kx = 0; kx < 8; kx++) {
            float wv = sdw[ky*8 + kx];
            a0 += wv*row[kx];
            a1 += wv*row[kx+1];
            a2 += wv*row[kx+2];
            a3 += wv*row[kx+3];
        }
    }
    float* up = g_u + (size_t)bc*HW + (size_t)(y0+oy)*WIMG + x0 + ox;
    *(float4*)up = make_float4(a0,a1,a2,a3);
}

// ---------------- launch ----------------
extern "C" void kernel_launch(void* const* d_in, const int* in_sizes, int n_in,
                              void* d_out, int out_size)
{
    const float* x1       = (const float*)d_in[0];
    const float* x2       = (const float*)d_in[1];
    const float* qkv_w    = (const float*)d_in[2];
    const float* rel_bias = (const float*)d_in[3];
    const float* dw_w     = (const float*)d_in[4];
    const float* bn_g     = (const float*)d_in[5];
    const float* bn_b     = (const float*)d_in[6];
    const float* bn_m     = (const float*)d_in[7];
    const float* bn_v     = (const float*)d_in[8];
    const float* pw_w     = (const float*)d_in[9];
    float* out = (float*)d_out;

    prep_kernel<<<256, 256>>>(pw_w, bn_g, bn_b, bn_m, bn_v);
    bias_prep<<<dim3(NHH, 4, 8), 32>>>(rel_bias);
    qkv_gemm<<<dim3(256, 4, 4), 256>>>(x1, x2, qkv_w);
    attn_kernel<<<dim3(2048, 8), 128>>>();
    pool_kernel<<<dim3((TPL + 255)/256, CC, BB), 256>>>();
    dw_kernel<<<dim3(8, 8, BB*CC), 256>>>(dw_w);
    pw_gemm<<<dim3(256, 2, BB), 256>>>(out);
}

// round 10
// speedup vs baseline: 1.5538x; 1.5538x over previous
#include <cuda_runtime.h>
#include <math.h>

// Problem constants (fixed by setup_inputs)
#define HW    65536          // 256*256
#define WIMG  256
#define CC    256
#define BB    2
#define NHH   16
#define DHH   16
#define TP    257            // pooled plane dim (H+1)
#define TPL   (TP*TP)

#define QSCALE 0.3606737602222409f    // 0.25 * log2(e)
#define LOG2E  1.4426950408889634f

// ---------------- scratch (device globals; no allocs allowed) ----------------
static __device__ float g_q [BB*CC*HW];
static __device__ float g_k [BB*CC*HW];
static __device__ float g_v1[BB*CC*HW];
static __device__ float g_v2[BB*CC*HW];
static __device__ float g_o [BB*CC*HW];
static __device__ float g_t [BB*CC*TPL];
static __device__ float g_u [BB*CC*HW];
static __device__ float g_pwf[CC*CC];
static __device__ float g_pwb[CC];
static __device__ float g_biasf[NHH*4*8*128*4];   // bias in mma C-fragment layout

// ---------------- prep: fold BN into pointwise weights ----------------
__global__ void prep_kernel(const float* __restrict__ pw,
                            const float* __restrict__ gamma,
                            const float* __restrict__ beta,
                            const float* __restrict__ mean,
                            const float* __restrict__ var)
{
    __shared__ float red[256];
    int o = blockIdx.x, c = threadIdx.x;
    float inv = gamma[c] * rsqrtf(var[c] + 1e-5f);
    float w = pw[o*CC + c];
    g_pwf[o*CC + c] = w * inv;
    red[c] = w * (beta[c] - mean[c]*inv);
    __syncthreads();
    for (int s = 128; s > 0; s >>= 1) {
        if (c < s) red[c] += red[c+s];
        __syncthreads();
    }
    if (c == 0) g_pwb[o] = red[0];
}

// ---------------- bias prep: rel-pos bias in mma C-fragment layout, x log2e ----
__global__ void bias_prep(const float* __restrict__ rel_bias)
{
    int h = blockIdx.x, mi = blockIdx.y, ni = blockIdx.z;
    int lane = threadIdx.x;
    int g = lane >> 2, t = lane & 3;
    float v[4];
    #pragma unroll
    for (int rr = 0; rr < 2; rr++) {
        int i = mi*16 + g + rr*8;
        #pragma unroll
        for (int cc = 0; cc < 2; cc++) {
            int j = ni*8 + 2*t + cc;
            int idx = ((i>>3) - (j>>3) + 7)*15 + ((i&7) - (j&7) + 7);
            v[rr*2 + cc] = LOG2E * rel_bias[idx*NHH + h];
        }
    }
    *(float4*)&g_biasf[(((h*4 + mi)*8 + ni)*128 + lane*4)] =
        make_float4(v[0], v[1], v[2], v[3]);
}

// ---------------- tf32 helpers ----------------
__device__ __forceinline__ unsigned f2tf(float x) {
    unsigned r; asm("cvt.rna.tf32.f32 %0, %1;" : "=r"(r) : "f"(x)); return r;
}
__device__ __forceinline__ float ex2(float x) {
    float r; asm("ex2.approx.ftz.f32 %0, %1;" : "=f"(r) : "f"(x)); return r;
}
__device__ __forceinline__ void mma8(float* c, const unsigned* a, const unsigned* b) {
    asm volatile(
        "mma.sync.aligned.m16n8k8.row.col.f32.tf32.tf32.f32 "
        "{%0,%1,%2,%3},{%4,%5,%6,%7},{%8,%9},{%0,%1,%2,%3};"
        : "+f"(c[0]), "+f"(c[1]), "+f"(c[2]), "+f"(c[3])
        : "r"(a[0]), "r"(a[1]), "r"(a[2]), "r"(a[3]), "r"(b[0]), "r"(b[1]));
}

// ---------------- core tf32 GEMM tile: 128(M) x 128(N), K=256 ----------------
// (reverted to R5-proven version: 8 warps (4m x 2n), warp tile 32x64, BK=16)
#define SA 136

__device__ __forceinline__ void gemm128_tf32(
    const float* __restrict__ wb,
    const float* __restrict__ xb,
    float* __restrict__ ob,
    int n0,
    const float* __restrict__ bias)
{
    __shared__ __align__(16) unsigned As[16*SA];
    __shared__ __align__(16) unsigned Bs[16*SA];

    int tid  = threadIdx.x;
    int lane = tid & 31, warp = tid >> 5;
    int wm = warp >> 1, wn = warp & 1;
    int gid = lane >> 2, tig = lane & 3;

    float acc[2][8][4];
    #pragma unroll
    for (int mt = 0; mt < 2; mt++)
        #pragma unroll
        for (int nt = 0; nt < 8; nt++)
            #pragma unroll
            for (int i = 0; i < 4; i++) acc[mt][nt][i] = 0.f;

    int arow = tid >> 1,  akq = (tid & 1) * 8;
    int brow = tid >> 4,  bnq = (tid & 15) * 8;

    for (int k0 = 0; k0 < CC; k0 += 16) {
        float4 a0 = *(const float4*)(wb + (size_t)arow*CC + k0 + akq);
        float4 a1 = *(const float4*)(wb + (size_t)arow*CC + k0 + akq + 4);
        float4 b0 = *(const float4*)(xb + (size_t)(k0 + brow)*HW + n0 + bnq);
        float4 b1 = *(const float4*)(xb + (size_t)(k0 + brow)*HW + n0 + bnq + 4);
        __syncthreads();
        As[(akq+0)*SA + arow] = f2tf(a0.x);
        As[(akq+1)*SA + arow] = f2tf(a0.y);
        As[(akq+2)*SA + arow] = f2tf(a0.z);
        As[(akq+3)*SA + arow] = f2tf(a0.w);
        As[(akq+4)*SA + arow] = f2tf(a1.x);
        As[(akq+5)*SA + arow] = f2tf(a1.y);
        As[(akq+6)*SA + arow] = f2tf(a1.z);
        As[(akq+7)*SA + arow] = f2tf(a1.w);
        *(uint4*)&Bs[brow*SA + bnq]     = make_uint4(f2tf(b0.x), f2tf(b0.y), f2tf(b0.z), f2tf(b0.w));
        *(uint4*)&Bs[brow*SA + bnq + 4] = make_uint4(f2tf(b1.x), f2tf(b1.y), f2tf(b1.z), f2tf(b1.w));
        __syncthreads();

        #pragma unroll
        for (int kk = 0; kk < 16; kk += 8) {
            unsigned af[2][4], bf[8][2];
            #pragma unroll
            for (int mt = 0; mt < 2; mt++) {
                int m = wm*32 + mt*16 + gid;
                af[mt][0] = As[(kk+tig  )*SA + m];
                af[mt][1] = As[(kk+tig  )*SA + m + 8];
                af[mt][2] = As[(kk+tig+4)*SA + m];
                af[mt][3] = As[(kk+tig+4)*SA + m + 8];
            }
            #pragma unroll
            for (int nt = 0; nt < 8; nt++) {
                int n = wn*64 + nt*8 + gid;
                bf[nt][0] = Bs[(kk+tig  )*SA + n];
                bf[nt][1] = Bs[(kk+tig+4)*SA + n];
            }
            #pragma unroll
            for (int mt = 0; mt < 2; mt++)
                #pragma unroll
                for (int nt = 0; nt < 8; nt++)
                    mma8(acc[mt][nt], af[mt], bf[nt]);
        }
    }

    #pragma unroll
    for (int mt = 0; mt < 2; mt++) {
        int r0 = wm*32 + mt*16 + gid;
        float bia0 = bias ? bias[r0]     : 0.f;
        float bia1 = bias ? bias[r0 + 8] : 0.f;
        #pragma unroll
        for (int nt = 0; nt < 8; nt++) {
            int c = n0 + wn*64 + nt*8 + 2*tig;
            *(float2*)(ob + (size_t)r0*HW + c) =
                make_float2(acc[mt][nt][0] + bia0, acc[mt][nt][1] + bia0);
            *(float2*)(ob + (size_t)(r0+8)*HW + c) =
                make_float2(acc[mt][nt][2] + bia1, acc[mt][nt][3] + bia1);
        }
    }
}

// ---------------- qkv GEMM (both inputs, one launch) ----------------
// z = which*2 + b. which=0: x1 -> q (W rows 0..255), v1; which=1: x2 -> k, v2.
__global__ void __launch_bounds__(256) qkv_gemm(const float* __restrict__ x1,
                                                const float* __restrict__ x2,
                                                const float* __restrict__ Wq)
{
    int z = blockIdx.z;
    int which = z >> 1, b = z & 1;
    int by = blockIdx.y;
    int n0 = blockIdx.x * 128;
    const float* X = which ? x2 : x1;
    float* outA = which ? g_k  : g_q;
    float* outB = which ? g_v2 : g_v1;
    int wrowA   = which ? 256 : 0;
    const float* wb;
    float* ob;
    if (by < 2) { wb = Wq + (size_t)(wrowA + by*128)*CC;
                  ob = outA + (size_t)b*CC*HW + (size_t)(by*128)*HW; }
    else        { wb = Wq + (size_t)(512 + (by-2)*128)*CC;
                  ob = outB + (size_t)b*CC*HW + (size_t)((by-2)*128)*HW; }
    const float* xb = X + (size_t)b*CC*HW;
    gemm128_tf32(wb, xb, ob, n0, nullptr);
}

// ---------------- pointwise GEMM (BN folded, tf32) ----------------
__global__ void __launch_bounds__(256) pw_gemm(float* __restrict__ out)
{
    int b  = blockIdx.z;
    int by = blockIdx.y;
    int n0 = blockIdx.x * 128;
    const float* wb = g_pwf + (size_t)(by*128)*CC;
    const float* xb = g_u + (size_t)b*CC*HW;
    float* ob = out + (size_t)b*CC*HW + (size_t)(by*128)*HW;
    gemm128_tf32(wb, xb, ob, n0, g_pwb + by*128);
}

// ---------------- window attention: tensor-core (mma tf32) ----------------
// o = 0.5*( softmax(q k^T*0.25 + bias) @ (v1-v2) + sum_k v2 )
// block = 1 window x 1 head, 4 warps; warp owns 16 queries (one m-tile).
// smem holds tf32 bit patterns (q pre-scaled), d-major, token stride 72.
#define TS 72

__global__ void __launch_bounds__(128, 5) attn_kernel()
{
    int wid = blockIdx.x;                 // 0..2047
    int h   = blockIdx.y;                 // 0..15
    int b   = wid >> 10;
    int wy  = (wid >> 5) & 31;
    int wx  = wid & 31;
    int tid = threadIdx.x;
    int lane = tid & 31;
    int mt   = tid >> 5;                  // m-tile 0..3 (16 queries each)
    int g = lane >> 2, t = lane & 3;

    __shared__ unsigned sq [16*TS];       // tf32(q * 0.25*log2e)
    __shared__ unsigned sk [16*TS];       // tf32(k)
    __shared__ unsigned svd[16*TS];       // tf32(0.5*(v1-v2))
    __shared__ float svs[16];             // 0.5*sum_k v2

    if (tid < 16) svs[tid] = 0.f;
    __syncthreads();

    // load window tile for this head (1024 elems, 8 iters)
    for (int e = tid; e < 1024; e += 128) {
        int dd = e >> 6, tk = e & 63;
        size_t ga = ((size_t)b*CC + h*DHH + dd)*HW
                  + (size_t)(wy*8 + (tk>>3))*WIMG + wx*8 + (tk&7);
        sq[dd*TS + tk] = f2tf(g_q[ga] * QSCALE);
        sk[dd*TS + tk] = f2tf(g_k[ga]);
        float v1 = g_v1[ga], v2 = g_v2[ga];
        svd[dd*TS + tk] = f2tf(0.5f*(v1 - v2));
        float s = 0.5f*v2;                // all 32 lanes share dd
        #pragma unroll
        for (int o = 16; o > 0; o >>= 1) s += __shfl_xor_sync(0xffffffffu, s, o);
        if (lane == 0) atomicAdd(&svs[dd], s);
    }
    __syncthreads();

    // Q A-fragments for my 16 queries (2 k-chunks)
    int r0q = mt*16 + g;
    unsigned aq[2][4];
    #pragma unroll
    for (int kc = 0; kc < 2; kc++) {
        aq[kc][0] = sq[(kc*8+t  )*TS + r0q];
        aq[kc][1] = sq[(kc*8+t  )*TS + r0q + 8];
        aq[kc][2] = sq[(kc*8+t+4)*TS + r0q];
        aq[kc][3] = sq[(kc*8+t+4)*TS + r0q + 8];
    }

    // S accumulators initialized with bias fragments (already x log2e)
    float acc[8][4];
    #pragma unroll
    for (int ni = 0; ni < 8; ni++) {
        float4 bv = *(const float4*)&g_biasf[(((h*4 + mt)*8 + ni)*128 + lane*4)];
        acc[ni][0] = bv.x; acc[ni][1] = bv.y;
        acc[ni][2] = bv.z; acc[ni][3] = bv.w;
    }

    // S = (0.25*log2e)*Q K^T + log2e*bias
    #pragma unroll
    for (int ni = 0; ni < 8; ni++) {
        unsigned bk[2][2];
        #pragma unroll
        for (int kc = 0; kc < 2; kc++) {
            bk[kc][0] = sk[(kc*8+t  )*TS + ni*8 + g];
            bk[kc][1] = sk[(kc*8+t+4)*TS + ni*8 + g];
        }
        mma8(acc[ni], aq[0], bk[0]);
        mma8(acc[ni], aq[1], bk[1]);
    }

    // softmax (base-2): rows g (regs 0,1) and g+8 (regs 2,3)
    {
        float m0 = -1e30f, m1 = -1e30f;
        #pragma unroll
        for (int ni = 0; ni < 8; ni++) {
            m0 = fmaxf(m0, fmaxf(acc[ni][0], acc[ni][1]));
            m1 = fmaxf(m1, fmaxf(acc[ni][2], acc[ni][3]));
        }
        m0 = fmaxf(m0, __shfl_xor_sync(0xffffffffu, m0, 1));
        m0 = fmaxf(m0, __shfl_xor_sync(0xffffffffu, m0, 2));
        m1 = fmaxf(m1, __shfl_xor_sync(0xffffffffu, m1, 1));
        m1 = fmaxf(m1, __shfl_xor_sync(0xffffffffu, m1, 2));
        float s0 = 0.f, s1 = 0.f;
        #pragma unroll
        for (int ni = 0; ni < 8; ni++) {
            float p0 = ex2(acc[ni][0] - m0);
            float p1 = ex2(acc[ni][1] - m0);
            float p2 = ex2(acc[ni][2] - m1);
            float p3 = ex2(acc[ni][3] - m1);
            acc[ni][0] = p0; acc[ni][1] = p1;
            acc[ni][2] = p2; acc[ni][3] = p3;
            s0 += p0 + p1; s1 += p2 + p3;
        }
        s0 += __shfl_xor_sync(0xffffffffu, s0, 1);
        s0 += __shfl_xor_sync(0xffffffffu, s0, 2);
        s1 += __shfl_xor_sync(0xffffffffu, s1, 1);
        s1 += __shfl_xor_sync(0xffffffffu, s1, 2);
        float i0 = 1.0f / s0, i1 = 1.0f / s1;
        #pragma unroll
        for (int ni = 0; ni < 8; ni++) {
            acc[ni][0] = __uint_as_float(f2tf(acc[ni][0]*i0));
            acc[ni][1] = __uint_as_float(f2tf(acc[ni][1]*i0));
            acc[ni][2] = __uint_as_float(f2tf(acc[ni][2]*i1));
            acc[ni][3] = __uint_as_float(f2tf(acc[ni][3]*i1));
        }
    }

    // AV accumulators initialized with 0.5*sum_k v2 (cols = d)
    float av[2][4];
    #pragma unroll
    for (int no = 0; no < 2; no++) {
        float c0 = svs[no*8 + 2*t];
        float c1 = svs[no*8 + 2*t + 1];
        av[no][0] = c0; av[no][1] = c1;
        av[no][2] = c0; av[no][3] = c1;
    }

    // AV: P @ (0.5*(v1-v2)); P C-layout -> A-layout via quad shuffles
    int src0 = (g << 2) | (t >> 1);
    int src1 = src0 + 2;
    bool odd = (t & 1);
    #pragma unroll
    for (int kc2 = 0; kc2 < 8; kc2++) {
        float r0 = acc[kc2][0], r1 = acc[kc2][1];
        float r2 = acc[kc2][2], r3 = acc[kc2][3];
        float x00 = __shfl_sync(0xffffffffu, r0, src0);
        float x01 = __shfl_sync(0xffffffffu, r1, src0);
        float x02 = __shfl_sync(0xffffffffu, r2, src0);
        float x03 = __shfl_sync(0xffffffffu, r3, src0);
        float x10 = __shfl_sync(0xffffffffu, r0, src1);
        float x11 = __shfl_sync(0xffffffffu, r1, src1);
        float x12 = __shfl_sync(0xffffffffu, r2, src1);
        float x13 = __shfl_sync(0xffffffffu, r3, src1);
        unsigned pa[4];
        pa[0] = __float_as_uint(odd ? x01 : x00);
        pa[1] = __float_as_uint(odd ? x03 : x02);
        pa[2] = __float_as_uint(odd ? x11 : x10);
        pa[3] = __float_as_uint(odd ? x13 : x12);
        unsigned bv[2][2];
        #pragma unroll
        for (int no = 0; no < 2; no++) {
            bv[no][0] = svd[(no*8+g)*TS + kc2*8 + t];
            bv[no][1] = svd[(no*8+g)*TS + kc2*8 + t + 4];
        }
        mma8(av[0], pa, bv[0]);
        mma8(av[1], pa, bv[1]);
    }

    // write out (0.5 factors already folded)
    size_t hb = ((size_t)b*CC + h*DHH)*HW + (size_t)(wy*8)*WIMG + wx*8;
    int r0 = mt*16 + g;
    int r1 = r0 + 8;
    #pragma unroll
    for (int no = 0; no < 2; no++) {
        int d0 = no*8 + 2*t;
        g_o[hb + (size_t)(d0  )*HW + (r0>>3)*WIMG + (r0&7)] = av[no][0];
        g_o[hb + (size_t)(d0+1)*HW + (r0>>3)*WIMG + (r0&7)] = av[no][1];
        g_o[hb + (size_t)(d0  )*HW + (r1>>3)*WIMG + (r1&7)] = av[no][2];
        g_o[hb + (size_t)(d0+1)*HW + (r1>>3)*WIMG + (r1&7)] = av[no][3];
    }
}

// ---------------- directional avg pools + pad_out ----------------
__global__ void pool_kernel()
{
    int p = blockIdx.x*256 + threadIdx.x;
    if (p >= TPL) return;
    int c = blockIdx.y, b = blockIdx.z;
    int y = p / TP, x = p - y*TP;
    const float* ob = g_o + ((size_t)b*CC + c)*HW;
    float val = 0.f;
    if (y < 256 && x < 256) {
        float sx = 0.f, sy = 0.f;
        #pragma unroll
        for (int t = 0; t < 8; t++) {
            int r = y - 3 + t;
            if (r >= 0 && r <= 256) sx += ob[(r == 256 ? 254 : r)*WIMG + x];
            int cl = x - 3 + t;
            if (cl >= 0 && cl <= 256) sy += ob[y*WIMG + (cl == 256 ? 254 : cl)];
        }
        val = (sx + sy)*0.125f;
    }
    g_t[((size_t)b*CC + c)*TPL + p] = val;
}

// ---------------- depthwise 8x8 conv (pad 3) over t[257x257] -> u[256x256] ----
__global__ void __launch_bounds__(256) dw_kernel(const float* __restrict__ dw)
{
    __shared__ float st[39][41];
    __shared__ float sdw[64];
    int bc = blockIdx.z;
    int y0 = blockIdx.y*32, x0 = blockIdx.x*32;
    const float* tb = g_t + (size_t)bc*TPL;
    int tid = threadIdx.x;
    if (tid < 64) sdw[tid] = dw[(bc & 255)*64 + tid];
    for (int idx = tid; idx < 39*39; idx += 256) {
        int r = idx / 39, cl = idx - r*39;
        int gy = y0 - 3 + r, gx = x0 - 3 + cl;
        float v = 0.f;
        if (gy >= 0 && gy < TP && gx >= 0 && gx < TP) v = tb[gy*TP + gx];
        st[r][cl] = v;
    }
    __syncthreads();
    int oy = tid >> 3, ox = (tid & 7)*4;
    float a0 = 0.f, a1 = 0.f, a2 = 0.f, a3 = 0.f;
    #pragma unroll
    for (int ky = 0; ky < 8; ky++) {
        const float* row = &st[oy+ky][ox];
        #pragma unroll
        for (int kx = 0; kx < 8; kx++) {
            float wv = sdw[ky*8 + kx];
            a0 += wv*row[kx];
            a1 += wv*row[kx+1];
            a2 += wv*row[kx+2];
            a3 += wv*row[kx+3];
        }
    }
    float* up = g_u + (size_t)bc*HW + (size_t)(y0+oy)*WIMG + x0 + ox;
    *(float4*)up = make_float4(a0,a1,a2,a3);
}

// ---------------- launch ----------------
extern "C" void kernel_launch(void* const* d_in, const int* in_sizes, int n_in,
                              void* d_out, int out_size)
{
    const float* x1       = (const float*)d_in[0];
    const float* x2       = (const float*)d_in[1];
    const float* qkv_w    = (const float*)d_in[2];
    const float* rel_bias = (const float*)d_in[3];
    const float* dw_w     = (const float*)d_in[4];
    const float* bn_g     = (const float*)d_in[5];
    const float* bn_b     = (const float*)d_in[6];
    const float* bn_m     = (const float*)d_in[7];
    const float* bn_v     = (const float*)d_in[8];
    const float* pw_w     = (const float*)d_in[9];
    float* out = (float*)d_out;

    prep_kernel<<<256, 256>>>(pw_w, bn_g, bn_b, bn_m, bn_v);
    bias_prep<<<dim3(NHH, 4, 8), 32>>>(rel_bias);
    qkv_gemm<<<dim3(512, 4, 4), 256>>>(x1, x2, qkv_w);
    attn_kernel<<<dim3(2048, NHH), 128>>>();
    pool_kernel<<<dim3((TPL + 255)/256, CC, BB), 256>>>();
    dw_kernel<<<dim3(8, 8, BB*CC), 256>>>(dw_w);
    pw_gemm<<<dim3(512, 2, BB), 256>>>(out);
}

// round 11
// speedup vs baseline: 1.6642x; 1.0711x over previous
#include <cuda_runtime.h>
#include <math.h>

// Problem constants (fixed by setup_inputs)
#define HW    65536          // 256*256
#define WIMG  256
#define CC    256
#define BB    2
#define NHH   16
#define DHH   16
#define TP    257            // pooled plane dim (H+1)
#define TPL   (TP*TP)

#define QSCALE 0.3606737602222409f    // 0.25 * log2(e)
#define LOG2E  1.4426950408889634f

// ---------------- scratch (device globals; no allocs allowed) ----------------
static __device__ float g_q [BB*CC*HW];
static __device__ float g_k [BB*CC*HW];
static __device__ float g_v1[BB*CC*HW];
static __device__ float g_v2[BB*CC*HW];
static __device__ float g_o [BB*CC*HW];
static __device__ float g_u [BB*CC*HW];
static __device__ float g_pwf[CC*CC];
static __device__ float g_pwb[CC];
static __device__ float g_biasf[NHH*4*8*128*4];   // bias in mma C-fragment layout

// ---------------- prep: fold BN into pointwise weights ----------------
__global__ void prep_kernel(const float* __restrict__ pw,
                            const float* __restrict__ gamma,
                            const float* __restrict__ beta,
                            const float* __restrict__ mean,
                            const float* __restrict__ var)
{
    __shared__ float red[256];
    int o = blockIdx.x, c = threadIdx.x;
    float inv = gamma[c] * rsqrtf(var[c] + 1e-5f);
    float w = pw[o*CC + c];
    g_pwf[o*CC + c] = w * inv;
    red[c] = w * (beta[c] - mean[c]*inv);
    __syncthreads();
    for (int s = 128; s > 0; s >>= 1) {
        if (c < s) red[c] += red[c+s];
        __syncthreads();
    }
    if (c == 0) g_pwb[o] = red[0];
}

// ---------------- bias prep: rel-pos bias in mma C-fragment layout, x log2e ----
__global__ void bias_prep(const float* __restrict__ rel_bias)
{
    int h = blockIdx.x, mi = blockIdx.y, ni = blockIdx.z;
    int lane = threadIdx.x;
    int g = lane >> 2, t = lane & 3;
    float v[4];
    #pragma unroll
    for (int rr = 0; rr < 2; rr++) {
        int i = mi*16 + g + rr*8;
        #pragma unroll
        for (int cc = 0; cc < 2; cc++) {
            int j = ni*8 + 2*t + cc;
            int idx = ((i>>3) - (j>>3) + 7)*15 + ((i&7) - (j&7) + 7);
            v[rr*2 + cc] = LOG2E * rel_bias[idx*NHH + h];
        }
    }
    *(float4*)&g_biasf[(((h*4 + mi)*8 + ni)*128 + lane*4)] =
        make_float4(v[0], v[1], v[2], v[3]);
}

// ---------------- tf32 helpers ----------------
__device__ __forceinline__ unsigned f2tf(float x) {
    unsigned r; asm("cvt.rna.tf32.f32 %0, %1;" : "=r"(r) : "f"(x)); return r;
}
__device__ __forceinline__ float ex2(float x) {
    float r; asm("ex2.approx.ftz.f32 %0, %1;" : "=f"(r) : "f"(x)); return r;
}
__device__ __forceinline__ void mma8(float* c, const unsigned* a, const unsigned* b) {
    asm volatile(
        "mma.sync.aligned.m16n8k8.row.col.f32.tf32.tf32.f32 "
        "{%0,%1,%2,%3},{%4,%5,%6,%7},{%8,%9},{%0,%1,%2,%3};"
        : "+f"(c[0]), "+f"(c[1]), "+f"(c[2]), "+f"(c[3])
        : "r"(a[0]), "r"(a[1]), "r"(a[2]), "r"(a[3]), "r"(b[0]), "r"(b[1]));
}

// ---------------- core tf32 GEMM tile: 128(M) x 128(N), K=256 ----------------
// 8 warps (4m x 2n), warp tile 32x64, BK=16, DOUBLE-buffered smem.
#define SA 136

__device__ __forceinline__ void gemm128_tf32(
    const float* __restrict__ wb,
    const float* __restrict__ xb,
    float* __restrict__ ob,
    int n0,
    const float* __restrict__ bias)
{
    __shared__ __align__(16) unsigned As[2][16*SA];
    __shared__ __align__(16) unsigned Bs[2][16*SA];

    int tid  = threadIdx.x;
    int lane = tid & 31, warp = tid >> 5;
    int wm = warp >> 1, wn = warp & 1;
    int gid = lane >> 2, tig = lane & 3;

    float acc[2][8][4];
    #pragma unroll
    for (int mt = 0; mt < 2; mt++)
        #pragma unroll
        for (int nt = 0; nt < 8; nt++)
            #pragma unroll
            for (int i = 0; i < 4; i++) acc[mt][nt][i] = 0.f;

    int arow = tid >> 1,  akq = (tid & 1) * 8;
    int brow = tid >> 4,  bnq = (tid & 15) * 8;

    // prologue: load + store k-block 0 into buffer 0
    {
        float4 a0 = *(const float4*)(wb + (size_t)arow*CC + akq);
        float4 a1 = *(const float4*)(wb + (size_t)arow*CC + akq + 4);
        float4 b0 = *(const float4*)(xb + (size_t)brow*HW + n0 + bnq);
        float4 b1 = *(const float4*)(xb + (size_t)brow*HW + n0 + bnq + 4);
        As[0][(akq+0)*SA + arow] = f2tf(a0.x);
        As[0][(akq+1)*SA + arow] = f2tf(a0.y);
        As[0][(akq+2)*SA + arow] = f2tf(a0.z);
        As[0][(akq+3)*SA + arow] = f2tf(a0.w);
        As[0][(akq+4)*SA + arow] = f2tf(a1.x);
        As[0][(akq+5)*SA + arow] = f2tf(a1.y);
        As[0][(akq+6)*SA + arow] = f2tf(a1.z);
        As[0][(akq+7)*SA + arow] = f2tf(a1.w);
        *(uint4*)&Bs[0][brow*SA + bnq]     = make_uint4(f2tf(b0.x), f2tf(b0.y), f2tf(b0.z), f2tf(b0.w));
        *(uint4*)&Bs[0][brow*SA + bnq + 4] = make_uint4(f2tf(b1.x), f2tf(b1.y), f2tf(b1.z), f2tf(b1.w));
    }
    __syncthreads();

    #pragma unroll 2
    for (int it = 0; it < 16; it++) {
        int p = it & 1;
        float4 a0, a1, b0, b1;
        if (it < 15) {
            int k0 = (it + 1) * 16;
            a0 = *(const float4*)(wb + (size_t)arow*CC + k0 + akq);
            a1 = *(const float4*)(wb + (size_t)arow*CC + k0 + akq + 4);
            b0 = *(const float4*)(xb + (size_t)(k0 + brow)*HW + n0 + bnq);
            b1 = *(const float4*)(xb + (size_t)(k0 + brow)*HW + n0 + bnq + 4);
        }

        #pragma unroll
        for (int kk = 0; kk < 16; kk += 8) {
            unsigned af[2][4], bf[8][2];
            #pragma unroll
            for (int mt = 0; mt < 2; mt++) {
                int m = wm*32 + mt*16 + gid;
                af[mt][0] = As[p][(kk+tig  )*SA + m];
                af[mt][1] = As[p][(kk+tig  )*SA + m + 8];
                af[mt][2] = As[p][(kk+tig+4)*SA + m];
                af[mt][3] = As[p][(kk+tig+4)*SA + m + 8];
            }
            #pragma unroll
            for (int nt = 0; nt < 8; nt++) {
                int n = wn*64 + nt*8 + gid;
                bf[nt][0] = Bs[p][(kk+tig  )*SA + n];
                bf[nt][1] = Bs[p][(kk+tig+4)*SA + n];
            }
            #pragma unroll
            for (int mt = 0; mt < 2; mt++)
                #pragma unroll
                for (int nt = 0; nt < 8; nt++)
                    mma8(acc[mt][nt], af[mt], bf[nt]);
        }

        if (it < 15) {
            int q = p ^ 1;
            As[q][(akq+0)*SA + arow] = f2tf(a0.x);
            As[q][(akq+1)*SA + arow] = f2tf(a0.y);
            As[q][(akq+2)*SA + arow] = f2tf(a0.z);
            As[q][(akq+3)*SA + arow] = f2tf(a0.w);
            As[q][(akq+4)*SA + arow] = f2tf(a1.x);
            As[q][(akq+5)*SA + arow] = f2tf(a1.y);
            As[q][(akq+6)*SA + arow] = f2tf(a1.z);
            As[q][(akq+7)*SA + arow] = f2tf(a1.w);
            *(uint4*)&Bs[q][brow*SA + bnq]     = make_uint4(f2tf(b0.x), f2tf(b0.y), f2tf(b0.z), f2tf(b0.w));
            *(uint4*)&Bs[q][brow*SA + bnq + 4] = make_uint4(f2tf(b1.x), f2tf(b1.y), f2tf(b1.z), f2tf(b1.w));
        }
        __syncthreads();
    }

    #pragma unroll
    for (int mt = 0; mt < 2; mt++) {
        int r0 = wm*32 + mt*16 + gid;
        float bia0 = bias ? bias[r0]     : 0.f;
        float bia1 = bias ? bias[r0 + 8] : 0.f;
        #pragma unroll
        for (int nt = 0; nt < 8; nt++) {
            int c = n0 + wn*64 + nt*8 + 2*tig;
            *(float2*)(ob + (size_t)r0*HW + c) =
                make_float2(acc[mt][nt][0] + bia0, acc[mt][nt][1] + bia0);
            *(float2*)(ob + (size_t)(r0+8)*HW + c) =
                make_float2(acc[mt][nt][2] + bia1, acc[mt][nt][3] + bia1);
        }
    }
}

// ---------------- qkv GEMM (both inputs, one launch) ----------------
// z = which*2 + b. which=0: x1 -> q (W rows 0..255), v1; which=1: x2 -> k, v2.
__global__ void __launch_bounds__(256, 2) qkv_gemm(const float* __restrict__ x1,
                                                   const float* __restrict__ x2,
                                                   const float* __restrict__ Wq)
{
    int z = blockIdx.z;
    int which = z >> 1, b = z & 1;
    int by = blockIdx.y;
    int n0 = blockIdx.x * 128;
    const float* X = which ? x2 : x1;
    float* outA = which ? g_k  : g_q;
    float* outB = which ? g_v2 : g_v1;
    int wrowA   = which ? 256 : 0;
    const float* wb;
    float* ob;
    if (by < 2) { wb = Wq + (size_t)(wrowA + by*128)*CC;
                  ob = outA + (size_t)b*CC*HW + (size_t)(by*128)*HW; }
    else        { wb = Wq + (size_t)(512 + (by-2)*128)*CC;
                  ob = outB + (size_t)b*CC*HW + (size_t)((by-2)*128)*HW; }
    const float* xb = X + (size_t)b*CC*HW;
    gemm128_tf32(wb, xb, ob, n0, nullptr);
}

// ---------------- pointwise GEMM (BN folded, tf32) ----------------
__global__ void __launch_bounds__(256, 2) pw_gemm(float* __restrict__ out)
{
    int b  = blockIdx.z;
    int by = blockIdx.y;
    int n0 = blockIdx.x * 128;
    const float* wb = g_pwf + (size_t)(by*128)*CC;
    const float* xb = g_u + (size_t)b*CC*HW;
    float* ob = out + (size_t)b*CC*HW + (size_t)(by*128)*HW;
    gemm128_tf32(wb, xb, ob, n0, g_pwb + by*128);
}

// ---------------- window attention: tensor-core (mma tf32) ----------------
// o = 0.5*( softmax(q k^T*0.25 + bias) @ (v1-v2) + sum_k v2 )
// block = 1 window x 1 head, 4 warps; warp owns 16 queries (one m-tile).
#define TS 72

__global__ void __launch_bounds__(128, 5) attn_kernel()
{
    int wid = blockIdx.x;                 // 0..2047
    int h   = blockIdx.y;                 // 0..15
    int b   = wid >> 10;
    int wy  = (wid >> 5) & 31;
    int wx  = wid & 31;
    int tid = threadIdx.x;
    int lane = tid & 31;
    int mt   = tid >> 5;                  // m-tile 0..3 (16 queries each)
    int g = lane >> 2, t = lane & 3;

    __shared__ unsigned sq [16*TS];       // tf32(q * 0.25*log2e)
    __shared__ unsigned sk [16*TS];       // tf32(k)
    __shared__ unsigned svd[16*TS];       // tf32(0.5*(v1-v2))
    __shared__ float svs[16];             // 0.5*sum_k v2

    if (tid < 16) svs[tid] = 0.f;
    __syncthreads();

    for (int e = tid; e < 1024; e += 128) {
        int dd = e >> 6, tk = e & 63;
        size_t ga = ((size_t)b*CC + h*DHH + dd)*HW
                  + (size_t)(wy*8 + (tk>>3))*WIMG + wx*8 + (tk&7);
        sq[dd*TS + tk] = f2tf(g_q[ga] * QSCALE);
        sk[dd*TS + tk] = f2tf(g_k[ga]);
        float v1 = g_v1[ga], v2 = g_v2[ga];
        svd[dd*TS + tk] = f2tf(0.5f*(v1 - v2));
        float s = 0.5f*v2;
        #pragma unroll
        for (int o = 16; o > 0; o >>= 1) s += __shfl_xor_sync(0xffffffffu, s, o);
        if (lane == 0) atomicAdd(&svs[dd], s);
    }
    __syncthreads();

    int r0q = mt*16 + g;
    unsigned aq[2][4];
    #pragma unroll
    for (int kc = 0; kc < 2; kc++) {
        aq[kc][0] = sq[(kc*8+t  )*TS + r0q];
        aq[kc][1] = sq[(kc*8+t  )*TS + r0q + 8];
        aq[kc][2] = sq[(kc*8+t+4)*TS + r0q];
        aq[kc][3] = sq[(kc*8+t+4)*TS + r0q + 8];
    }

    float acc[8][4];
    #pragma unroll
    for (int ni = 0; ni < 8; ni++) {
        float4 bv = *(const float4*)&g_biasf[(((h*4 + mt)*8 + ni)*128 + lane*4)];
        acc[ni][0] = bv.x; acc[ni][1] = bv.y;
        acc[ni][2] = bv.z; acc[ni][3] = bv.w;
    }

    #pragma unroll
    for (int ni = 0; ni < 8; ni++) {
        unsigned bk[2][2];
        #pragma unroll
        for (int kc = 0; kc < 2; kc++) {
            bk[kc][0] = sk[(kc*8+t  )*TS + ni*8 + g];
            bk[kc][1] = sk[(kc*8+t+4)*TS + ni*8 + g];
        }
        mma8(acc[ni], aq[0], bk[0]);
        mma8(acc[ni], aq[1], bk[1]);
    }

    {
        float m0 = -1e30f, m1 = -1e30f;
        #pragma unroll
        for (int ni = 0; ni < 8; ni++) {
            m0 = fmaxf(m0, fmaxf(acc[ni][0], acc[ni][1]));
            m1 = fmaxf(m1, fmaxf(acc[ni][2], acc[ni][3]));
        }
        m0 = fmaxf(m0, __shfl_xor_sync(0xffffffffu, m0, 1));
        m0 = fmaxf(m0, __shfl_xor_sync(0xffffffffu, m0, 2));
        m1 = fmaxf(m1, __shfl_xor_sync(0xffffffffu, m1, 1));
        m1 = fmaxf(m1, __shfl_xor_sync(0xffffffffu, m1, 2));
        float s0 = 0.f, s1 = 0.f;
        #pragma unroll
        for (int ni = 0; ni < 8; ni++) {
            float p0 = ex2(acc[ni][0] - m0);
            float p1 = ex2(acc[ni][1] - m0);
            float p2 = ex2(acc[ni][2] - m1);
            float p3 = ex2(acc[ni][3] - m1);
            acc[ni][0] = p0; acc[ni][1] = p1;
            acc[ni][2] = p2; acc[ni][3] = p3;
            s0 += p0 + p1; s1 += p2 + p3;
        }
        s0 += __shfl_xor_sync(0xffffffffu, s0, 1);
        s0 += __shfl_xor_sync(0xffffffffu, s0, 2);
        s1 += __shfl_xor_sync(0xffffffffu, s1, 1);
        s1 += __shfl_xor_sync(0xffffffffu, s1, 2);
        float i0 = 1.0f / s0, i1 = 1.0f / s1;
        #pragma unroll
        for (int ni = 0; ni < 8; ni++) {
            acc[ni][0] = __uint_as_float(f2tf(acc[ni][0]*i0));
            acc[ni][1] = __uint_as_float(f2tf(acc[ni][1]*i0));
            acc[ni][2] = __uint_as_float(f2tf(acc[ni][2]*i1));
            acc[ni][3] = __uint_as_float(f2tf(acc[ni][3]*i1));
        }
    }

    float av[2][4];
    #pragma unroll
    for (int no = 0; no < 2; no++) {
        float c0 = svs[no*8 + 2*t];
        float c1 = svs[no*8 + 2*t + 1];
        av[no][0] = c0; av[no][1] = c1;
        av[no][2] = c0; av[no][3] = c1;
    }

    int src0 = (g << 2) | (t >> 1);
    int src1 = src0 + 2;
    bool odd = (t & 1);
    #pragma unroll
    for (int kc2 = 0; kc2 < 8; kc2++) {
        float r0 = acc[kc2][0], r1 = acc[kc2][1];
        float r2 = acc[kc2][2], r3 = acc[kc2][3];
        float x00 = __shfl_sync(0xffffffffu, r0, src0);
        float x01 = __shfl_sync(0xffffffffu, r1, src0);
        float x02 = __shfl_sync(0xffffffffu, r2, src0);
        float x03 = __shfl_sync(0xffffffffu, r3, src0);
        float x10 = __shfl_sync(0xffffffffu, r0, src1);
        float x11 = __shfl_sync(0xffffffffu, r1, src1);
        float x12 = __shfl_sync(0xffffffffu, r2, src1);
        float x13 = __shfl_sync(0xffffffffu, r3, src1);
        unsigned pa[4];
        pa[0] = __float_as_uint(odd ? x01 : x00);
        pa[1] = __float_as_uint(odd ? x03 : x02);
        pa[2] = __float_as_uint(odd ? x11 : x10);
        pa[3] = __float_as_uint(odd ? x13 : x12);
        unsigned bv[2][2];
        #pragma unroll
        for (int no = 0; no < 2; no++) {
            bv[no][0] = svd[(no*8+g)*TS + kc2*8 + t];
            bv[no][1] = svd[(no*8+g)*TS + kc2*8 + t + 4];
        }
        mma8(av[0], pa, bv[0]);
        mma8(av[1], pa, bv[1]);
    }

    size_t hb = ((size_t)b*CC + h*DHH)*HW + (size_t)(wy*8)*WIMG + wx*8;
    int r0 = mt*16 + g;
    int r1 = r0 + 8;
    #pragma unroll
    for (int no = 0; no < 2; no++) {
        int d0 = no*8 + 2*t;
        g_o[hb + (size_t)(d0  )*HW + (r0>>3)*WIMG + (r0&7)] = av[no][0];
        g_o[hb + (size_t)(d0+1)*HW + (r0>>3)*WIMG + (r0&7)] = av[no][1];
        g_o[hb + (size_t)(d0  )*HW + (r1>>3)*WIMG + (r1&7)] = av[no][2];
        g_o[hb + (size_t)(d0+1)*HW + (r1>>3)*WIMG + (r1&7)] = av[no][3];
    }
}

// ---------------- FUSED directional avg pools + pad_out + depthwise 8x8 ------
// t[y][x] = 0.125*(col8sum + row8sum) of o (reflect idx 256 -> 254, zero outside),
// t row/col 256 = 0; then u = dwconv8x8(t, pad 3). One 32x32 output tile/block.
__global__ void __launch_bounds__(256) pooldw_kernel(const float* __restrict__ dw)
{
    __shared__ float so[47][48];
    __shared__ float st[39][41];
    __shared__ float sdw[64];
    int bc = blockIdx.z;                       // b*256 + c
    int y0 = blockIdx.y*32, x0 = blockIdx.x*32;
    const float* ob = g_o + (size_t)bc*HW;
    int tid = threadIdx.x;
    if (tid < 64) sdw[tid] = dw[(bc & 255)*64 + tid];

    // o tile with halo: gy = y0-6+r, gx = x0-6+c; both-axis reflect @256, 0 outside
    for (int idx = tid; idx < 47*47; idx += 256) {
        int r = idx / 47, c = idx - r*47;
        int gy = y0 - 6 + r, gx = x0 - 6 + c;
        float v = 0.f;
        if (gy >= 0 && gy <= 256 && gx >= 0 && gx <= 256) {
            int yy = (gy == 256) ? 254 : gy;
            int xx = (gx == 256) ? 254 : gx;
            v = ob[yy*WIMG + xx];
        }
        so[r][c] = v;
    }
    __syncthreads();

    // t tile: ty = y0-3+r, tx = x0-3+c; nonzero only for ty,tx in [0,256)
    for (int idx = tid; idx < 39*39; idx += 256) {
        int r = idx / 39, c = idx - r*39;
        int ty = y0 - 3 + r, tx = x0 - 3 + c;
        float v = 0.f;
        if (ty >= 0 && ty < 256 && tx >= 0 && tx < 256) {
            float sx = 0.f, sy = 0.f;
            #pragma unroll
            for (int d2 = 0; d2 < 8; d2++) {
                sx += so[r + d2][c + 3];     // rows ty-3..ty+4, col tx
                sy += so[r + 3][c + d2];     // row ty, cols tx-3..tx+4
            }
            v = (sx + sy)*0.125f;
        }
        st[r][c] = v;
    }
    __syncthreads();

    // depthwise 8x8 over t tile
    int oy = tid >> 3, ox = (tid & 7)*4;
    float a0 = 0.f, a1 = 0.f, a2 = 0.f, a3 = 0.f;
    #pragma unroll
    for (int ky = 0; ky < 8; ky++) {
        const float* row = &st[oy+ky][ox];
        #pragma unroll
        for (int kx = 0; kx < 8; kx++) {
            float wv = sdw[ky*8 + kx];
            a0 += wv*row[kx];
            a1 += wv*row[kx+1];
            a2 += wv*row[kx+2];
            a3 += wv*row[kx+3];
        }
    }
    float* up = g_u + (size_t)bc*HW + (size_t)(y0+oy)*WIMG + x0 + ox;
    *(float4*)up = make_float4(a0,a1,a2,a3);
}

// ---------------- launch ----------------
extern "C" void kernel_launch(void* const* d_in, const int* in_sizes, int n_in,
                              void* d_out, int out_size)
{
    const float* x1       = (const float*)d_in[0];
    const float* x2       = (const float*)d_in[1];
    const float* qkv_w    = (const float*)d_in[2];
    const float* rel_bias = (const float*)d_in[3];
    const float* dw_w     = (const float*)d_in[4];
    const float* bn_g     = (const float*)d_in[5];
    const float* bn_b     = (const float*)d_in[6];
    const float* bn_m     = (const float*)d_in[7];
    const float* bn_v     = (const float*)d_in[8];
    const float* pw_w     = (const float*)d_in[9];
    float* out = (float*)d_out;

    prep_kernel<<<256, 256>>>(pw_w, bn_g, bn_b, bn_m, bn_v);
    bias_prep<<<dim3(NHH, 4, 8), 32>>>(rel_bias);
    qkv_gemm<<<dim3(512, 4, 4), 256>>>(x1, x2, qkv_w);
    attn_kernel<<<dim3(2048, NHH), 128>>>();
    pooldw_kernel<<<dim3(8, 8, BB*CC), 256>>>(dw_w);
    pw_gemm<<<dim3(512, 2, BB), 256>>>(out);
}

// round 12
// speedup vs baseline: 1.7885x; 1.0747x over previous
#include <cuda_runtime.h>
#include <math.h>

// Problem constants (fixed by setup_inputs)
#define HW    65536          // 256*256
#define WIMG  256
#define CC    256
#define BB    2
#define NHH   16
#define DHH   16
#define TP    257
#define TPL   (TP*TP)

#define QSCALE 0.3606737602222409f    // 0.25 * log2(e)
#define LOG2E  1.4426950408889634f

// ---------------- scratch (device globals; no allocs allowed) ----------------
// q/k/v1/v2/o: WINDOW-major layout: arr[(b*16+h)*1048576 + w*1024 + d*64 + tok]
static __device__ float g_q [BB*CC*HW];
static __device__ float g_k [BB*CC*HW];
static __device__ float g_v1[BB*CC*HW];
static __device__ float g_v2[BB*CC*HW];
static __device__ float g_o [BB*CC*HW];
static __device__ float g_u [BB*CC*HW];
static __device__ float g_pwf[CC*CC];
static __device__ float g_pwb[CC];
static __device__ float g_biasf[NHH*4*8*128*4];   // bias in mma C-fragment layout

// ---------------- prep: fold BN into pointwise weights ----------------
__global__ void prep_kernel(const float* __restrict__ pw,
                            const float* __restrict__ gamma,
                            const float* __restrict__ beta,
                            const float* __restrict__ mean,
                            const float* __restrict__ var)
{
    __shared__ float red[256];
    int o = blockIdx.x, c = threadIdx.x;
    float inv = gamma[c] * rsqrtf(var[c] + 1e-5f);
    float w = pw[o*CC + c];
    g_pwf[o*CC + c] = w * inv;
    red[c] = w * (beta[c] - mean[c]*inv);
    __syncthreads();
    for (int s = 128; s > 0; s >>= 1) {
        if (c < s) red[c] += red[c+s];
        __syncthreads();
    }
    if (c == 0) g_pwb[o] = red[0];
}

// ---------------- bias prep: rel-pos bias in mma C-fragment layout, x log2e ----
__global__ void bias_prep(const float* __restrict__ rel_bias)
{
    int h = blockIdx.x, mi = blockIdx.y, ni = blockIdx.z;
    int lane = threadIdx.x;
    int g = lane >> 2, t = lane & 3;
    float v[4];
    #pragma unroll
    for (int rr = 0; rr < 2; rr++) {
        int i = mi*16 + g + rr*8;
        #pragma unroll
        for (int cc = 0; cc < 2; cc++) {
            int j = ni*8 + 2*t + cc;
            int idx = ((i>>3) - (j>>3) + 7)*15 + ((i&7) - (j&7) + 7);
            v[rr*2 + cc] = LOG2E * rel_bias[idx*NHH + h];
        }
    }
    *(float4*)&g_biasf[(((h*4 + mi)*8 + ni)*128 + lane*4)] =
        make_float4(v[0], v[1], v[2], v[3]);
}

// ---------------- tf32 helpers ----------------
__device__ __forceinline__ unsigned f2tf(float x) {
    unsigned r; asm("cvt.rna.tf32.f32 %0, %1;" : "=r"(r) : "f"(x)); return r;
}
__device__ __forceinline__ float ex2(float x) {
    float r; asm("ex2.approx.ftz.f32 %0, %1;" : "=f"(r) : "f"(x)); return r;
}
__device__ __forceinline__ void mma8(float* c, const unsigned* a, const unsigned* b) {
    asm volatile(
        "mma.sync.aligned.m16n8k8.row.col.f32.tf32.tf32.f32 "
        "{%0,%1,%2,%3},{%4,%5,%6,%7},{%8,%9},{%0,%1,%2,%3};"
        : "+f"(c[0]), "+f"(c[1]), "+f"(c[2]), "+f"(c[3])
        : "r"(a[0]), "r"(a[1]), "r"(a[2]), "r"(a[3]), "r"(b[0]), "r"(b[1]));
}

// ---------------- core tf32 GEMM tile: 128(M) x 128(N), K=256 ----------------
// 8 warps (4m x 2n), warp tile 32x64, BK=16, double-buffered smem.
// wmode=0: ob[row*HW + n0+col] (+bias). wmode=1: window-major store, ob is
// array base offset to (b, h0); channel row r maps h=h0+(r>>4), d=r&15.
#define SA 136

__device__ __forceinline__ void gemm128_tf32(
    const float* __restrict__ wb,
    const float* __restrict__ xb,
    float* __restrict__ ob,
    int n0,
    const float* __restrict__ bias,
    int wmode)
{
    __shared__ __align__(16) unsigned As[2][16*SA];
    __shared__ __align__(16) unsigned Bs[2][16*SA];

    int tid  = threadIdx.x;
    int lane = tid & 31, warp = tid >> 5;
    int wm = warp >> 1, wn = warp & 1;
    int gid = lane >> 2, tig = lane & 3;

    float acc[2][8][4];
    #pragma unroll
    for (int mt = 0; mt < 2; mt++)
        #pragma unroll
        for (int nt = 0; nt < 8; nt++)
            #pragma unroll
            for (int i = 0; i < 4; i++) acc[mt][nt][i] = 0.f;

    int arow = tid >> 1,  akq = (tid & 1) * 8;
    int brow = tid >> 4,  bnq = (tid & 15) * 8;

    {
        float4 a0 = *(const float4*)(wb + (size_t)arow*CC + akq);
        float4 a1 = *(const float4*)(wb + (size_t)arow*CC + akq + 4);
        float4 b0 = *(const float4*)(xb + (size_t)brow*HW + n0 + bnq);
        float4 b1 = *(const float4*)(xb + (size_t)brow*HW + n0 + bnq + 4);
        As[0][(akq+0)*SA + arow] = f2tf(a0.x);
        As[0][(akq+1)*SA + arow] = f2tf(a0.y);
        As[0][(akq+2)*SA + arow] = f2tf(a0.z);
        As[0][(akq+3)*SA + arow] = f2tf(a0.w);
        As[0][(akq+4)*SA + arow] = f2tf(a1.x);
        As[0][(akq+5)*SA + arow] = f2tf(a1.y);
        As[0][(akq+6)*SA + arow] = f2tf(a1.z);
        As[0][(akq+7)*SA + arow] = f2tf(a1.w);
        *(uint4*)&Bs[0][brow*SA + bnq]     = make_uint4(f2tf(b0.x), f2tf(b0.y), f2tf(b0.z), f2tf(b0.w));
        *(uint4*)&Bs[0][brow*SA + bnq + 4] = make_uint4(f2tf(b1.x), f2tf(b1.y), f2tf(b1.z), f2tf(b1.w));
    }
    __syncthreads();

    #pragma unroll 2
    for (int it = 0; it < 16; it++) {
        int p = it & 1;
        float4 a0, a1, b0, b1;
        if (it < 15) {
            int k0 = (it + 1) * 16;
            a0 = *(const float4*)(wb + (size_t)arow*CC + k0 + akq);
            a1 = *(const float4*)(wb + (size_t)arow*CC + k0 + akq + 4);
            b0 = *(const float4*)(xb + (size_t)(k0 + brow)*HW + n0 + bnq);
            b1 = *(const float4*)(xb + (size_t)(k0 + brow)*HW + n0 + bnq + 4);
        }

        #pragma unroll
        for (int kk = 0; kk < 16; kk += 8) {
            unsigned af[2][4], bf[8][2];
            #pragma unroll
            for (int mt = 0; mt < 2; mt++) {
                int m = wm*32 + mt*16 + gid;
                af[mt][0] = As[p][(kk+tig  )*SA + m];
                af[mt][1] = As[p][(kk+tig  )*SA + m + 8];
                af[mt][2] = As[p][(kk+tig+4)*SA + m];
                af[mt][3] = As[p][(kk+tig+4)*SA + m + 8];
            }
            #pragma unroll
            for (int nt = 0; nt < 8; nt++) {
                int n = wn*64 + nt*8 + gid;
                bf[nt][0] = Bs[p][(kk+tig  )*SA + n];
                bf[nt][1] = Bs[p][(kk+tig+4)*SA + n];
            }
            #pragma unroll
            for (int mt = 0; mt < 2; mt++)
                #pragma unroll
                for (int nt = 0; nt < 8; nt++)
                    mma8(acc[mt][nt], af[mt], bf[nt]);
        }

        if (it < 15) {
            int q = p ^ 1;
            As[q][(akq+0)*SA + arow] = f2tf(a0.x);
            As[q][(akq+1)*SA + arow] = f2tf(a0.y);
            As[q][(akq+2)*SA + arow] = f2tf(a0.z);
            As[q][(akq+3)*SA + arow] = f2tf(a0.w);
            As[q][(akq+4)*SA + arow] = f2tf(a1.x);
            As[q][(akq+5)*SA + arow] = f2tf(a1.y);
            As[q][(akq+6)*SA + arow] = f2tf(a1.z);
            As[q][(akq+7)*SA + arow] = f2tf(a1.w);
            *(uint4*)&Bs[q][brow*SA + bnq]     = make_uint4(f2tf(b0.x), f2tf(b0.y), f2tf(b0.z), f2tf(b0.w));
            *(uint4*)&Bs[q][brow*SA + bnq + 4] = make_uint4(f2tf(b1.x), f2tf(b1.y), f2tf(b1.z), f2tf(b1.w));
        }
        __syncthreads();
    }

    if (wmode) {
        // window-major store: one image row y per block
        int y = n0 >> 8, xb0 = n0 & 255;
        int wy = y >> 3, ty = y & 7;
        #pragma unroll
        for (int mt = 0; mt < 2; mt++) {
            int hloc = wm*2 + mt;                 // channel>>4 within this 128-row tile
            #pragma unroll
            for (int nt = 0; nt < 8; nt++) {
                int x = xb0 + wn*64 + nt*8 + 2*tig;
                size_t a0 = ((size_t)hloc*1024 + wy*32 + (x>>3))*16;
                int tx = ty*8 + (x&7);
                *(float2*)(ob + (a0 + gid    )*64 + tx) =
                    make_float2(acc[mt][nt][0], acc[mt][nt][1]);
                *(float2*)(ob + (a0 + gid + 8)*64 + tx) =
                    make_float2(acc[mt][nt][2], acc[mt][nt][3]);
            }
        }
    } else {
        #pragma unroll
        for (int mt = 0; mt < 2; mt++) {
            int r0 = wm*32 + mt*16 + gid;
            float bia0 = bias ? bias[r0]     : 0.f;
            float bia1 = bias ? bias[r0 + 8] : 0.f;
            #pragma unroll
            for (int nt = 0; nt < 8; nt++) {
                int c = n0 + wn*64 + nt*8 + 2*tig;
                *(float2*)(ob + (size_t)r0*HW + c) =
                    make_float2(acc[mt][nt][0] + bia0, acc[mt][nt][1] + bia0);
                *(float2*)(ob + (size_t)(r0+8)*HW + c) =
                    make_float2(acc[mt][nt][2] + bia1, acc[mt][nt][3] + bia1);
            }
        }
    }
}

// ---------------- qkv GEMM (both inputs, one launch; window-major out) -------
__global__ void __launch_bounds__(256, 2) qkv_gemm(const float* __restrict__ x1,
                                                   const float* __restrict__ x2,
                                                   const float* __restrict__ Wq)
{
    int z = blockIdx.z;
    int which = z >> 1, b = z & 1;
    int by = blockIdx.y;
    int n0 = blockIdx.x * 128;
    const float* X = which ? x2 : x1;
    float* outA = which ? g_k  : g_q;
    float* outB = which ? g_v2 : g_v1;
    int wrowA   = which ? 256 : 0;
    const float* wb;
    float* ob;
    if (by < 2) { wb = Wq + (size_t)(wrowA + by*128)*CC;
                  ob = outA + ((size_t)(b*16 + by*8) << 20); }
    else        { wb = Wq + (size_t)(512 + (by-2)*128)*CC;
                  ob = outB + ((size_t)(b*16 + (by-2)*8) << 20); }
    const float* xb = X + (size_t)b*CC*HW;
    gemm128_tf32(wb, xb, ob, n0, nullptr, 1);
}

// ---------------- pointwise GEMM (BN folded, tf32, image layout) ----------------
__global__ void __launch_bounds__(256, 2) pw_gemm(float* __restrict__ out)
{
    int b  = blockIdx.z;
    int by = blockIdx.y;
    int n0 = blockIdx.x * 128;
    const float* wb = g_pwf + (size_t)(by*128)*CC;
    const float* xb = g_u + (size_t)b*CC*HW;
    float* ob = out + (size_t)b*CC*HW + (size_t)(by*128)*HW;
    gemm128_tf32(wb, xb, ob, n0, g_pwb + by*128, 0);
}

// ---------------- window attention: tensor-core (mma tf32) ----------------
// o = 0.5*( softmax(q k^T*0.25 + bias) @ (v1-v2) + sum_k v2 )
// all tensors window-major: coalesced LDG.128 in, 4-sector stores out.
#define TS 72

__global__ void __launch_bounds__(128, 5) attn_kernel()
{
    int wid = blockIdx.x;                 // 0..2047
    int h   = blockIdx.y;                 // 0..15
    int b   = wid >> 10;
    int w   = wid & 1023;
    int tid = threadIdx.x;
    int lane = tid & 31;
    int mt   = tid >> 5;                  // m-tile 0..3 (16 queries each)
    int g = lane >> 2, t = lane & 3;

    __shared__ unsigned sq [16*TS];       // tf32(q * 0.25*log2e)
    __shared__ unsigned sk [16*TS];       // tf32(k)
    __shared__ unsigned svd[16*TS];       // tf32(0.5*(v1-v2))
    __shared__ float svs[16];             // 0.5*sum_k v2

    size_t wbase = ((size_t)((b*NHH + h)*1024 + w)) * 1024;

    // coalesced load: thread covers 8 consecutive tokens of one d
    {
        int j = tid & 7, dd = tid >> 3;
        int t0 = j*8;
        size_t off = wbase + dd*64 + t0;
        float4 qa = *(const float4*)(g_q + off), qb2 = *(const float4*)(g_q + off + 4);
        float4 ka = *(const float4*)(g_k + off), kb2 = *(const float4*)(g_k + off + 4);
        float4 va = *(const float4*)(g_v1 + off), vb2 = *(const float4*)(g_v1 + off + 4);
        float4 ua = *(const float4*)(g_v2 + off), ub2 = *(const float4*)(g_v2 + off + 4);
        unsigned* sp = &sq[dd*TS + t0];
        sp[0]=f2tf(qa.x*QSCALE); sp[1]=f2tf(qa.y*QSCALE); sp[2]=f2tf(qa.z*QSCALE); sp[3]=f2tf(qa.w*QSCALE);
        sp[4]=f2tf(qb2.x*QSCALE); sp[5]=f2tf(qb2.y*QSCALE); sp[6]=f2tf(qb2.z*QSCALE); sp[7]=f2tf(qb2.w*QSCALE);
        sp = &sk[dd*TS + t0];
        sp[0]=f2tf(ka.x); sp[1]=f2tf(ka.y); sp[2]=f2tf(ka.z); sp[3]=f2tf(ka.w);
        sp[4]=f2tf(kb2.x); sp[5]=f2tf(kb2.y); sp[6]=f2tf(kb2.z); sp[7]=f2tf(kb2.w);
        sp = &svd[dd*TS + t0];
        sp[0]=f2tf(0.5f*(va.x-ua.x)); sp[1]=f2tf(0.5f*(va.y-ua.y));
        sp[2]=f2tf(0.5f*(va.z-ua.z)); sp[3]=f2tf(0.5f*(va.w-ua.w));
        sp[4]=f2tf(0.5f*(vb2.x-ub2.x)); sp[5]=f2tf(0.5f*(vb2.y-ub2.y));
        sp[6]=f2tf(0.5f*(vb2.z-ub2.z)); sp[7]=f2tf(0.5f*(vb2.w-ub2.w));
        float s = 0.5f*(ua.x+ua.y+ua.z+ua.w+ub2.x+ub2.y+ub2.z+ub2.w);
        s += __shfl_xor_sync(0xffffffffu, s, 1);
        s += __shfl_xor_sync(0xffffffffu, s, 2);
        s += __shfl_xor_sync(0xffffffffu, s, 4);
        if (j == 0) svs[dd] = s;
    }
    __syncthreads();

    int r0q = mt*16 + g;
    unsigned aq[2][4];
    #pragma unroll
    for (int kc = 0; kc < 2; kc++) {
        aq[kc][0] = sq[(kc*8+t  )*TS + r0q];
        aq[kc][1] = sq[(kc*8+t  )*TS + r0q + 8];
        aq[kc][2] = sq[(kc*8+t+4)*TS + r0q];
        aq[kc][3] = sq[(kc*8+t+4)*TS + r0q + 8];
    }

    float acc[8][4];
    #pragma unroll
    for (int ni = 0; ni < 8; ni++) {
        float4 bv = *(const float4*)&g_biasf[(((h*4 + mt)*8 + ni)*128 + lane*4)];
        acc[ni][0] = bv.x; acc[ni][1] = bv.y;
        acc[ni][2] = bv.z; acc[ni][3] = bv.w;
    }

    #pragma unroll
    for (int ni = 0; ni < 8; ni++) {
        unsigned bk[2][2];
        #pragma unroll
        for (int kc = 0; kc < 2; kc++) {
            bk[kc][0] = sk[(kc*8+t  )*TS + ni*8 + g];
            bk[kc][1] = sk[(kc*8+t+4)*TS + ni*8 + g];
        }
        mma8(acc[ni], aq[0], bk[0]);
        mma8(acc[ni], aq[1], bk[1]);
    }

    {
        float m0 = -1e30f, m1 = -1e30f;
        #pragma unroll
        for (int ni = 0; ni < 8; ni++) {
            m0 = fmaxf(m0, fmaxf(acc[ni][0], acc[ni][1]));
            m1 = fmaxf(m1, fmaxf(acc[ni][2], acc[ni][3]));
        }
        m0 = fmaxf(m0, __shfl_xor_sync(0xffffffffu, m0, 1));
        m0 = fmaxf(m0, __shfl_xor_sync(0xffffffffu, m0, 2));
        m1 = fmaxf(m1, __shfl_xor_sync(0xffffffffu, m1, 1));
        m1 = fmaxf(m1, __shfl_xor_sync(0xffffffffu, m1, 2));
        float s0 = 0.f, s1 = 0.f;
        #pragma unroll
        for (int ni = 0; ni < 8; ni++) {
            float p0 = ex2(acc[ni][0] - m0);
            float p1 = ex2(acc[ni][1] - m0);
            float p2 = ex2(acc[ni][2] - m1);
            float p3 = ex2(acc[ni][3] - m1);
            acc[ni][0] = p0; acc[ni][1] = p1;
            acc[ni][2] = p2; acc[ni][3] = p3;
            s0 += p0 + p1; s1 += p2 + p3;
        }
        s0 += __shfl_xor_sync(0xffffffffu, s0, 1);
        s0 += __shfl_xor_sync(0xffffffffu, s0, 2);
        s1 += __shfl_xor_sync(0xffffffffu, s1, 1);
        s1 += __shfl_xor_sync(0xffffffffu, s1, 2);
        float i0 = 1.0f / s0, i1 = 1.0f / s1;
        #pragma unroll
        for (int ni = 0; ni < 8; ni++) {
            acc[ni][0] = __uint_as_float(f2tf(acc[ni][0]*i0));
            acc[ni][1] = __uint_as_float(f2tf(acc[ni][1]*i0));
            acc[ni][2] = __uint_as_float(f2tf(acc[ni][2]*i1));
            acc[ni][3] = __uint_as_float(f2tf(acc[ni][3]*i1));
        }
    }

    float av[2][4];
    #pragma unroll
    for (int no = 0; no < 2; no++) {
        float c0 = svs[no*8 + 2*t];
        float c1 = svs[no*8 + 2*t + 1];
        av[no][0] = c0; av[no][1] = c1;
        av[no][2] = c0; av[no][3] = c1;
    }

    int src0 = (g << 2) | (t >> 1);
    int src1 = src0 + 2;
    bool odd = (t & 1);
    #pragma unroll
    for (int kc2 = 0; kc2 < 8; kc2++) {
        float r0 = acc[kc2][0], r1 = acc[kc2][1];
        float r2 = acc[kc2][2], r3 = acc[kc2][3];
        float x00 = __shfl_sync(0xffffffffu, r0, src0);
        float x01 = __shfl_sync(0xffffffffu, r1, src0);
        float x02 = __shfl_sync(0xffffffffu, r2, src0);
        float x03 = __shfl_sync(0xffffffffu, r3, src0);
        float x10 = __shfl_sync(0xffffffffu, r0, src1);
        float x11 = __shfl_sync(0xffffffffu, r1, src1);
        float x12 = __shfl_sync(0xffffffffu, r2, src1);
        float x13 = __shfl_sync(0xffffffffu, r3, src1);
        unsigned pa[4];
        pa[0] = __float_as_uint(odd ? x01 : x00);
        pa[1] = __float_as_uint(odd ? x03 : x02);
        pa[2] = __float_as_uint(odd ? x11 : x10);
        pa[3] = __float_as_uint(odd ? x13 : x12);
        unsigned bv[2][2];
        #pragma unroll
        for (int no = 0; no < 2; no++) {
            bv[no][0] = svd[(no*8+g)*TS + kc2*8 + t];
            bv[no][1] = svd[(no*8+g)*TS + kc2*8 + t + 4];
        }
        mma8(av[0], pa, bv[0]);
        mma8(av[1], pa, bv[1]);
    }

    // window-major store: o[d*64 + query]
    float* op = g_o + wbase;
    int q0 = mt*16 + g;
    #pragma unroll
    for (int no = 0; no < 2; no++) {
        int d0 = no*8 + 2*t;
        op[(d0  )*64 + q0    ] = av[no][0];
        op[(d0+1)*64 + q0    ] = av[no][1];
        op[(d0  )*64 + q0 + 8] = av[no][2];
        op[(d0+1)*64 + q0 + 8] = av[no][3];
    }
}

// ---------------- FUSED pools + pad_out + depthwise (window-major o in) ------
__global__ void __launch_bounds__(256) pooldw_kernel(const float* __restrict__ dw)
{
    __shared__ float so[47][48];
    __shared__ float st[39][41];
    __shared__ float sdw[64];
    int bc = blockIdx.z;                       // b*256 + c
    int b = bc >> 8, c = bc & 255;
    int y0 = blockIdx.y*32, x0 = blockIdx.x*32;
    const float* ob = g_o + ((size_t)(b*16 + (c>>4)) << 20) + (size_t)(c & 15)*64;
    int tid = threadIdx.x;
    if (tid < 64) sdw[tid] = dw[c*64 + tid];

    // o tile with halo: both-axis reflect @256, 0 outside
    for (int idx = tid; idx < 47*47; idx += 256) {
        int r = idx / 47, cl = idx - r*47;
        int gy = y0 - 6 + r, gx = x0 - 6 + cl;
        float v = 0.f;
        if (gy >= 0 && gy <= 256 && gx >= 0 && gx <= 256) {
            int yy = (gy == 256) ? 254 : gy;
            int xx = (gx == 256) ? 254 : gx;
            v = ob[((size_t)((yy>>3)*32 + (xx>>3)))*1024 + (yy&7)*8 + (xx&7)];
        }
        so[r][cl] = v;
    }
    __syncthreads();

    for (int idx = tid; idx < 39*39; idx += 256) {
        int r = idx / 39, cl = idx - r*39;
        int ty = y0 - 3 + r, tx = x0 - 3 + cl;
        float v = 0.f;
        if (ty >= 0 && ty < 256 && tx >= 0 && tx < 256) {
            float sx = 0.f, sy = 0.f;
            #pragma unroll
            for (int d2 = 0; d2 < 8; d2++) {
                sx += so[r + d2][cl + 3];
                sy += so[r + 3][cl + d2];
            }
            v = (sx + sy)*0.125f;
        }
        st[r][cl] = v;
    }
    __syncthreads();

    int oy = tid >> 3, ox = (tid & 7)*4;
    float a0 = 0.f, a1 = 0.f, a2 = 0.f, a3 = 0.f;
    #pragma unroll
    for (int ky = 0; ky < 8; ky++) {
        const float* row = &st[oy+ky][ox];
        #pragma unroll
        for (int kx = 0; kx < 8; kx++) {
            float wv = sdw[ky*8 + kx];
            a0 += wv*row[kx];
            a1 += wv*row[kx+1];
            a2 += wv*row[kx+2];
            a3 += wv*row[kx+3];
        }
    }
    float* up = g_u + (size_t)bc*HW + (size_t)(y0+oy)*WIMG + x0 + ox;
    *(float4*)up = make_float4(a0,a1,a2,a3);
}

// ---------------- launch ----------------
extern "C" void kernel_launch(void* const* d_in, const int* in_sizes, int n_in,
                              void* d_out, int out_size)
{
    const float* x1       = (const float*)d_in[0];
    const float* x2       = (const float*)d_in[1];
    const float* qkv_w    = (const float*)d_in[2];
    const float* rel_bias = (const float*)d_in[3];
    const float* dw_w     = (const float*)d_in[4];
    const float* bn_g     = (const float*)d_in[5];
    const float* bn_b     = (const float*)d_in[6];
    const float* bn_m     = (const float*)d_in[7];
    const float* bn_v     = (const float*)d_in[8];
    const float* pw_w     = (const float*)d_in[9];
    float* out = (float*)d_out;

    prep_kernel<<<256, 256>>>(pw_w, bn_g, bn_b, bn_m, bn_v);
    bias_prep<<<dim3(NHH, 4, 8), 32>>>(rel_bias);
    qkv_gemm<<<dim3(512, 4, 4), 256>>>(x1, x2, qkv_w);
    attn_kernel<<<dim3(2048, NHH), 128>>>();
    pooldw_kernel<<<dim3(8, 8, BB*CC), 256>>>(dw_w);
    pw_gemm<<<dim3(512, 2, BB), 256>>>(out);
}

// round 13
// speedup vs baseline: 1.8673x; 1.0441x over previous
#include <cuda_runtime.h>
#include <math.h>

// Problem constants (fixed by setup_inputs)
#define HW    65536          // 256*256
#define WIMG  256
#define CC    256
#define BB    2
#define NHH   16
#define DHH   16

#define QSCALE 0.3606737602222409f    // 0.25 * log2(e)
#define LOG2E  1.4426950408889634f

// ---------------- scratch (device globals; no allocs allowed) ----------------
// q/k/vd/o: WINDOW-major: arr[(b*16+h)*1048576 + w*1024 + d*64 + tok]
static __device__ float g_q [BB*CC*HW];
static __device__ float g_k [BB*CC*HW];
static __device__ float g_vd[BB*CC*HW];            // W_v (x1 - x2)
static __device__ float g_o [BB*CC*HW];
static __device__ float g_u [BB*CC*HW];
static __device__ float g_pwf[CC*CC];
static __device__ float g_pwb[CC];
static __device__ float g_biasf[NHH*4*8*128*4];    // bias in mma C-fragment layout
static __device__ float g_sx [BB*CC*1024];         // per-window sums of x2
static __device__ float g_vs [BB*NHH*1024*16];     // 0.5 * sum_k v2, [bh][w][d]

// ---------------- prep: fold BN into pointwise weights ----------------
__global__ void prep_kernel(const float* __restrict__ pw,
                            const float* __restrict__ gamma,
                            const float* __restrict__ beta,
                            const float* __restrict__ mean,
                            const float* __restrict__ var)
{
    __shared__ float red[256];
    int o = blockIdx.x, c = threadIdx.x;
    float inv = gamma[c] * rsqrtf(var[c] + 1e-5f);
    float w = pw[o*CC + c];
    g_pwf[o*CC + c] = w * inv;
    red[c] = w * (beta[c] - mean[c]*inv);
    __syncthreads();
    for (int s = 128; s > 0; s >>= 1) {
        if (c < s) red[c] += red[c+s];
        __syncthreads();
    }
    if (c == 0) g_pwb[o] = red[0];
}

// ---------------- bias prep: rel-pos bias in mma C-fragment layout, x log2e ----
__global__ void bias_prep(const float* __restrict__ rel_bias)
{
    int h = blockIdx.x, mi = blockIdx.y, ni = blockIdx.z;
    int lane = threadIdx.x;
    int g = lane >> 2, t = lane & 3;
    float v[4];
    #pragma unroll
    for (int rr = 0; rr < 2; rr++) {
        int i = mi*16 + g + rr*8;
        #pragma unroll
        for (int cc = 0; cc < 2; cc++) {
            int j = ni*8 + 2*t + cc;
            int idx = ((i>>3) - (j>>3) + 7)*15 + ((i&7) - (j&7) + 7);
            v[rr*2 + cc] = LOG2E * rel_bias[idx*NHH + h];
        }
    }
    *(float4*)&g_biasf[(((h*4 + mi)*8 + ni)*128 + lane*4)] =
        make_float4(v[0], v[1], v[2], v[3]);
}

// ---------------- window sums of x2 ----------------
// g_sx[(b*256+c)*1024 + wy*32 + wx] = sum over 8x8 patch of x2[b][c]
__global__ void xsum_kernel(const float* __restrict__ x2)
{
    int tid = threadIdx.x;
    int wy = blockIdx.x, c = blockIdx.y, b = blockIdx.z;
    const float* xp = x2 + ((size_t)(b*CC + c))*HW + (size_t)(wy*8)*WIMG + tid;
    float s = 0.f;
    #pragma unroll
    for (int r = 0; r < 8; r++) s += xp[(size_t)r*WIMG];
    s += __shfl_xor_sync(0xffffffffu, s, 1);
    s += __shfl_xor_sync(0xffffffffu, s, 2);
    s += __shfl_xor_sync(0xffffffffu, s, 4);
    if ((tid & 7) == 0)
        g_sx[((size_t)(b*CC + c))*1024 + wy*32 + (tid >> 3)] = s;
}

// ---------------- tiny GEMM: g_vs = 0.5 * Wv @ g_sx ----------------
// block: (b, 16 windows); thread = output channel o (h=o>>4, d=o&15).
__global__ void __launch_bounds__(256) vs_gemm(const float* __restrict__ Wq)
{
    __shared__ float sS[256][16];
    __shared__ float sW[16][257];
    int tid = threadIdx.x;
    int w0 = blockIdx.x * 16, b = blockIdx.y;

    // load Sx2 tile: thread tid -> channel tid, 16 windows (contiguous)
    {
        const float* sp = g_sx + ((size_t)(b*CC + tid))*1024 + w0;
        float4 v0 = *(const float4*)(sp);
        float4 v1 = *(const float4*)(sp + 4);
        float4 v2 = *(const float4*)(sp + 8);
        float4 v3 = *(const float4*)(sp + 12);
        sS[tid][0]=v0.x; sS[tid][1]=v0.y; sS[tid][2]=v0.z; sS[tid][3]=v0.w;
        sS[tid][4]=v1.x; sS[tid][5]=v1.y; sS[tid][6]=v1.z; sS[tid][7]=v1.w;
        sS[tid][8]=v2.x; sS[tid][9]=v2.y; sS[tid][10]=v2.z; sS[tid][11]=v2.w;
        sS[tid][12]=v3.x; sS[tid][13]=v3.y; sS[tid][14]=v3.z; sS[tid][15]=v3.w;
    }

    float acc[16];
    #pragma unroll
    for (int j = 0; j < 16; j++) acc[j] = 0.f;

    for (int c0 = 0; c0 < CC; c0 += 16) {
        __syncthreads();
        {
            const float* wp = Wq + (size_t)(512 + tid)*CC + c0;
            float4 w0v = *(const float4*)(wp);
            float4 w1v = *(const float4*)(wp + 4);
            float4 w2v = *(const float4*)(wp + 8);
            float4 w3v = *(const float4*)(wp + 12);
            sW[0][tid]=w0v.x; sW[1][tid]=w0v.y; sW[2][tid]=w0v.z; sW[3][tid]=w0v.w;
            sW[4][tid]=w1v.x; sW[5][tid]=w1v.y; sW[6][tid]=w1v.z; sW[7][tid]=w1v.w;
            sW[8][tid]=w2v.x; sW[9][tid]=w2v.y; sW[10][tid]=w2v.z; sW[11][tid]=w2v.w;
            sW[12][tid]=w3v.x; sW[13][tid]=w3v.y; sW[14][tid]=w3v.z; sW[15][tid]=w3v.w;
        }
        __syncthreads();
        #pragma unroll
        for (int cc = 0; cc < 16; cc++) {
            float wv = sW[cc][tid];
            #pragma unroll
            for (int j = 0; j < 16; j++)
                acc[j] += wv * sS[c0 + cc][j];
        }
    }

    int h = tid >> 4, d = tid & 15;
    #pragma unroll
    for (int j = 0; j < 16; j++)
        g_vs[(((size_t)(b*NHH + h))*1024 + w0 + j)*16 + d] = 0.5f*acc[j];
}

// ---------------- tf32 helpers ----------------
__device__ __forceinline__ unsigned f2tf(float x) {
    unsigned r; asm("cvt.rna.tf32.f32 %0, %1;" : "=r"(r) : "f"(x)); return r;
}
__device__ __forceinline__ float ex2(float x) {
    float r; asm("ex2.approx.ftz.f32 %0, %1;" : "=f"(r) : "f"(x)); return r;
}
__device__ __forceinline__ void mma8(float* c, const unsigned* a, const unsigned* b) {
    asm volatile(
        "mma.sync.aligned.m16n8k8.row.col.f32.tf32.tf32.f32 "
        "{%0,%1,%2,%3},{%4,%5,%6,%7},{%8,%9},{%0,%1,%2,%3};"
        : "+f"(c[0]), "+f"(c[1]), "+f"(c[2]), "+f"(c[3])
        : "r"(a[0]), "r"(a[1]), "r"(a[2]), "r"(a[3]), "r"(b[0]), "r"(b[1]));
}

// ---------------- core tf32 GEMM tile: 128(M) x 128(N), K=256 ----------------
// 8 warps (4m x 2n), warp tile 32x64, BK=16, double-buffered smem.
// xb2 != nullptr: B operand is (xb - xb2). wmode=1: window-major store.
#define SA 136

__device__ __forceinline__ void gemm128_tf32(
    const float* __restrict__ wb,
    const float* __restrict__ xb,
    const float* __restrict__ xb2,
    float* __restrict__ ob,
    int n0,
    const float* __restrict__ bias,
    int wmode)
{
    __shared__ __align__(16) unsigned As[2][16*SA];
    __shared__ __align__(16) unsigned Bs[2][16*SA];

    int tid  = threadIdx.x;
    int lane = tid & 31, warp = tid >> 5;
    int wm = warp >> 1, wn = warp & 1;
    int gid = lane >> 2, tig = lane & 3;

    float acc[2][8][4];
    #pragma unroll
    for (int mt = 0; mt < 2; mt++)
        #pragma unroll
        for (int nt = 0; nt < 8; nt++)
            #pragma unroll
            for (int i = 0; i < 4; i++) acc[mt][nt][i] = 0.f;

    int arow = tid >> 1,  akq = (tid & 1) * 8;
    int brow = tid >> 4,  bnq = (tid & 15) * 8;

    {
        float4 a0 = *(const float4*)(wb + (size_t)arow*CC + akq);
        float4 a1 = *(const float4*)(wb + (size_t)arow*CC + akq + 4);
        float4 b0 = *(const float4*)(xb + (size_t)brow*HW + n0 + bnq);
        float4 b1 = *(const float4*)(xb + (size_t)brow*HW + n0 + bnq + 4);
        if (xb2) {
            float4 c0 = *(const float4*)(xb2 + (size_t)brow*HW + n0 + bnq);
            float4 c1 = *(const float4*)(xb2 + (size_t)brow*HW + n0 + bnq + 4);
            b0.x -= c0.x; b0.y -= c0.y; b0.z -= c0.z; b0.w -= c0.w;
            b1.x -= c1.x; b1.y -= c1.y; b1.z -= c1.z; b1.w -= c1.w;
        }
        As[0][(akq+0)*SA + arow] = f2tf(a0.x);
        As[0][(akq+1)*SA + arow] = f2tf(a0.y);
        As[0][(akq+2)*SA + arow] = f2tf(a0.z);
        As[0][(akq+3)*SA + arow] = f2tf(a0.w);
        As[0][(akq+4)*SA + arow] = f2tf(a1.x);
        As[0][(akq+5)*SA + arow] = f2tf(a1.y);
        As[0][(akq+6)*SA + arow] = f2tf(a1.z);
        As[0][(akq+7)*SA + arow] = f2tf(a1.w);
        *(uint4*)&Bs[0][brow*SA + bnq]     = make_uint4(f2tf(b0.x), f2tf(b0.y), f2tf(b0.z), f2tf(b0.w));
        *(uint4*)&Bs[0][brow*SA + bnq + 4] = make_uint4(f2tf(b1.x), f2tf(b1.y), f2tf(b1.z), f2tf(b1.w));
    }
    __syncthreads();

    #pragma unroll 2
    for (int it = 0; it < 16; it++) {
        int p = it & 1;
        float4 a0, a1, b0, b1;
        if (it < 15) {
            int k0 = (it + 1) * 16;
            a0 = *(const float4*)(wb + (size_t)arow*CC + k0 + akq);
            a1 = *(const float4*)(wb + (size_t)arow*CC + k0 + akq + 4);
            b0 = *(const float4*)(xb + (size_t)(k0 + brow)*HW + n0 + bnq);
            b1 = *(const float4*)(xb + (size_t)(k0 + brow)*HW + n0 + bnq + 4);
            if (xb2) {
                float4 c0 = *(const float4*)(xb2 + (size_t)(k0 + brow)*HW + n0 + bnq);
                float4 c1 = *(const float4*)(xb2 + (size_t)(k0 + brow)*HW + n0 + bnq + 4);
                b0.x -= c0.x; b0.y -= c0.y; b0.z -= c0.z; b0.w -= c0.w;
                b1.x -= c1.x; b1.y -= c1.y; b1.z -= c1.z; b1.w -= c1.w;
            }
        }

        #pragma unroll
        for (int kk = 0; kk < 16; kk += 8) {
            unsigned af[2][4], bf[8][2];
            #pragma unroll
            for (int mt = 0; mt < 2; mt++) {
                int m = wm*32 + mt*16 + gid;
                af[mt][0] = As[p][(kk+tig  )*SA + m];
                af[mt][1] = As[p][(kk+tig  )*SA + m + 8];
                af[mt][2] = As[p][(kk+tig+4)*SA + m];
                af[mt][3] = As[p][(kk+tig+4)*SA + m + 8];
            }
            #pragma unroll
            for (int nt = 0; nt < 8; nt++) {
                int n = wn*64 + nt*8 + gid;
                bf[nt][0] = Bs[p][(kk+tig  )*SA + n];
                bf[nt][1] = Bs[p][(kk+tig+4)*SA + n];
            }
            #pragma unroll
            for (int mt = 0; mt < 2; mt++)
                #pragma unroll
                for (int nt = 0; nt < 8; nt++)
                    mma8(acc[mt][nt], af[mt], bf[nt]);
        }

        if (it < 15) {
            int q = p ^ 1;
            As[q][(akq+0)*SA + arow] = f2tf(a0.x);
            As[q][(akq+1)*SA + arow] = f2tf(a0.y);
            As[q][(akq+2)*SA + arow] = f2tf(a0.z);
            As[q][(akq+3)*SA + arow] = f2tf(a0.w);
            As[q][(akq+4)*SA + arow] = f2tf(a1.x);
            As[q][(akq+5)*SA + arow] = f2tf(a1.y);
            As[q][(akq+6)*SA + arow] = f2tf(a1.z);
            As[q][(akq+7)*SA + arow] = f2tf(a1.w);
            *(uint4*)&Bs[q][brow*SA + bnq]     = make_uint4(f2tf(b0.x), f2tf(b0.y), f2tf(b0.z), f2tf(b0.w));
            *(uint4*)&Bs[q][brow*SA + bnq + 4] = make_uint4(f2tf(b1.x), f2tf(b1.y), f2tf(b1.z), f2tf(b1.w));
        }
        __syncthreads();
    }

    if (wmode) {
        int y = n0 >> 8, xb0 = n0 & 255;
        int wy = y >> 3, ty = y & 7;
        #pragma unroll
        for (int mt = 0; mt < 2; mt++) {
            int hloc = wm*2 + mt;
            #pragma unroll
            for (int nt = 0; nt < 8; nt++) {
                int x = xb0 + wn*64 + nt*8 + 2*tig;
                size_t a0 = ((size_t)hloc*1024 + wy*32 + (x>>3))*16;
                int tx = ty*8 + (x&7);
                *(float2*)(ob + (a0 + gid    )*64 + tx) =
                    make_float2(acc[mt][nt][0], acc[mt][nt][1]);
                *(float2*)(ob + (a0 + gid + 8)*64 + tx) =
                    make_float2(acc[mt][nt][2], acc[mt][nt][3]);
            }
        }
    } else {
        #pragma unroll
        for (int mt = 0; mt < 2; mt++) {
            int r0 = wm*32 + mt*16 + gid;
            float bia0 = bias ? bias[r0]     : 0.f;
            float bia1 = bias ? bias[r0 + 8] : 0.f;
            #pragma unroll
            for (int nt = 0; nt < 8; nt++) {
                int c = n0 + wn*64 + nt*8 + 2*tig;
                *(float2*)(ob + (size_t)r0*HW + c) =
                    make_float2(acc[mt][nt][0] + bia0, acc[mt][nt][1] + bia0);
                *(float2*)(ob + (size_t)(r0+8)*HW + c) =
                    make_float2(acc[mt][nt][2] + bia1, acc[mt][nt][3] + bia1);
            }
        }
    }
}

// ---------------- qkv GEMM: q from x1, k from x2, vd from (x1-x2) ------------
// grid (512, 6, 2); by 0,1 -> q; 2,3 -> k; 4,5 -> vd.
__global__ void __launch_bounds__(256, 2) qkv_gemm(const float* __restrict__ x1,
                                                   const float* __restrict__ x2,
                                                   const float* __restrict__ Wq)
{
    int b  = blockIdx.z;
    int by = blockIdx.y;
    int n0 = blockIdx.x * 128;
    const float* wb;
    const float* xa;
    const float* xd2 = nullptr;
    float* ob;
    if (by < 2) {
        wb = Wq + (size_t)(by*128)*CC;
        ob = g_q + ((size_t)(b*16 + by*8) << 20);
        xa = x1;
    } else if (by < 4) {
        wb = Wq + (size_t)(256 + (by-2)*128)*CC;
        ob = g_k + ((size_t)(b*16 + (by-2)*8) << 20);
        xa = x2;
    } else {
        wb = Wq + (size_t)(512 + (by-4)*128)*CC;
        ob = g_vd + ((size_t)(b*16 + (by-4)*8) << 20);
        xa = x1; xd2 = x2 + (size_t)b*CC*HW;
    }
    xa += (size_t)b*CC*HW;
    gemm128_tf32(wb, xa, xd2, ob, n0, nullptr, 1);
}

// ---------------- pointwise GEMM (BN folded, tf32, image layout) -------------
__global__ void __launch_bounds__(256, 2) pw_gemm(float* __restrict__ out)
{
    int b  = blockIdx.z;
    int by = blockIdx.y;
    int n0 = blockIdx.x * 128;
    const float* wb = g_pwf + (size_t)(by*128)*CC;
    const float* xb = g_u + (size_t)b*CC*HW;
    float* ob = out + (size_t)b*CC*HW + (size_t)(by*128)*HW;
    gemm128_tf32(wb, xb, nullptr, ob, n0, g_pwb + by*128, 0);
}

// ---------------- window attention: tensor-core (mma tf32) ----------------
// o = softmax(q k^T*0.25 + bias) @ (0.5*(v1-v2)) + 0.5*sum_k v2
#define TS 72

__global__ void __launch_bounds__(128, 5) attn_kernel()
{
    int wid = blockIdx.x;                 // 0..2047
    int h   = blockIdx.y;                 // 0..15
    int b   = wid >> 10;
    int w   = wid & 1023;
    int tid = threadIdx.x;
    int lane = tid & 31;
    int mt   = tid >> 5;                  // m-tile 0..3 (16 queries each)
    int g = lane >> 2, t = lane & 3;

    __shared__ unsigned sq [16*TS];       // tf32(q * 0.25*log2e)
    __shared__ unsigned sk [16*TS];       // tf32(k)
    __shared__ unsigned svd[16*TS];       // tf32(0.5*vd)
    __shared__ float svs[16];             // 0.5*sum_k v2

    size_t wbase = ((size_t)((b*NHH + h)*1024 + w)) * 1024;

    if (tid < 16) svs[tid] = g_vs[((size_t)((b*NHH + h)*1024 + w))*16 + tid];

    // coalesced load: thread covers 8 consecutive tokens of one d
    {
        int j = tid & 7, dd = tid >> 3;
        int t0 = j*8;
        size_t off = wbase + dd*64 + t0;
        float4 qa = *(const float4*)(g_q + off), qb2 = *(const float4*)(g_q + off + 4);
        float4 ka = *(const float4*)(g_k + off), kb2 = *(const float4*)(g_k + off + 4);
        float4 va = *(const float4*)(g_vd + off), vb2 = *(const float4*)(g_vd + off + 4);
        unsigned* sp = &sq[dd*TS + t0];
        sp[0]=f2tf(qa.x*QSCALE); sp[1]=f2tf(qa.y*QSCALE); sp[2]=f2tf(qa.z*QSCALE); sp[3]=f2tf(qa.w*QSCALE);
        sp[4]=f2tf(qb2.x*QSCALE); sp[5]=f2tf(qb2.y*QSCALE); sp[6]=f2tf(qb2.z*QSCALE); sp[7]=f2tf(qb2.w*QSCALE);
        sp = &sk[dd*TS + t0];
        sp[0]=f2tf(ka.x); sp[1]=f2tf(ka.y); sp[2]=f2tf(ka.z); sp[3]=f2tf(ka.w);
        sp[4]=f2tf(kb2.x); sp[5]=f2tf(kb2.y); sp[6]=f2tf(kb2.z); sp[7]=f2tf(kb2.w);
        sp = &svd[dd*TS + t0];
        sp[0]=f2tf(0.5f*va.x); sp[1]=f2tf(0.5f*va.y); sp[2]=f2tf(0.5f*va.z); sp[3]=f2tf(0.5f*va.w);
        sp[4]=f2tf(0.5f*vb2.x); sp[5]=f2tf(0.5f*vb2.y); sp[6]=f2tf(0.5f*vb2.z); sp[7]=f2tf(0.5f*vb2.w);
    }
    __syncthreads();

    int r0q = mt*16 + g;
    unsigned aq[2][4];
    #pragma unroll
    for (int kc = 0; kc < 2; kc++) {
        aq[kc][0] = sq[(kc*8+t  )*TS + r0q];
        aq[kc][1] = sq[(kc*8+t  )*TS + r0q + 8];
        aq[kc][2] = sq[(kc*8+t+4)*TS + r0q];
        aq[kc][3] = sq[(kc*8+t+4)*TS + r0q + 8];
    }

    float acc[8][4];
    #pragma unroll
    for (int ni = 0; ni < 8; ni++) {
        float4 bv = *(const float4*)&g_biasf[(((h*4 + mt)*8 + ni)*128 + lane*4)];
        acc[ni][0] = bv.x; acc[ni][1] = bv.y;
        acc[ni][2] = bv.z; acc[ni][3] = bv.w;
    }

    #pragma unroll
    for (int ni = 0; ni < 8; ni++) {
        unsigned bk[2][2];
        #pragma unroll
        for (int kc = 0; kc < 2; kc++) {
            bk[kc][0] = sk[(kc*8+t  )*TS + ni*8 + g];
            bk[kc][1] = sk[(kc*8+t+4)*TS + ni*8 + g];
        }
        mma8(acc[ni], aq[0], bk[0]);
        mma8(acc[ni], aq[1], bk[1]);
    }

    {
        float m0 = -1e30f, m1 = -1e30f;
        #pragma unroll
        for (int ni = 0; ni < 8; ni++) {
            m0 = fmaxf(m0, fmaxf(acc[ni][0], acc[ni][1]));
            m1 = fmaxf(m1, fmaxf(acc[ni][2], acc[ni][3]));
        }
        m0 = fmaxf(m0, __shfl_xor_sync(0xffffffffu, m0, 1));
        m0 = fmaxf(m0, __shfl_xor_sync(0xffffffffu, m0, 2));
        m1 = fmaxf(m1, __shfl_xor_sync(0xffffffffu, m1, 1));
        m1 = fmaxf(m1, __shfl_xor_sync(0xffffffffu, m1, 2));
        float s0 = 0.f, s1 = 0.f;
        #pragma unroll
        for (int ni = 0; ni < 8; ni++) {
            float p0 = ex2(acc[ni][0] - m0);
            float p1 = ex2(acc[ni][1] - m0);
            float p2 = ex2(acc[ni][2] - m1);
            float p3 = ex2(acc[ni][3] - m1);
            acc[ni][0] = p0; acc[ni][1] = p1;
            acc[ni][2] = p2; acc[ni][3] = p3;
            s0 += p0 + p1; s1 += p2 + p3;
        }
        s0 += __shfl_xor_sync(0xffffffffu, s0, 1);
        s0 += __shfl_xor_sync(0xffffffffu, s0, 2);
        s1 += __shfl_xor_sync(0xffffffffu, s1, 1);
        s1 += __shfl_xor_sync(0xffffffffu, s1, 2);
        float i0 = 1.0f / s0, i1 = 1.0f / s1;
        #pragma unroll
        for (int ni = 0; ni < 8; ni++) {
            acc[ni][0] = __uint_as_float(f2tf(acc[ni][0]*i0));
            acc[ni][1] = __uint_as_float(f2tf(acc[ni][1]*i0));
            acc[ni][2] = __uint_as_float(f2tf(acc[ni][2]*i1));
            acc[ni][3] = __uint_as_float(f2tf(acc[ni][3]*i1));
        }
    }

    float av[2][4];
    #pragma unroll
    for (int no = 0; no < 2; no++) {
        float c0 = svs[no*8 + 2*t];
        float c1 = svs[no*8 + 2*t + 1];
        av[no][0] = c0; av[no][1] = c1;
        av[no][2] = c0; av[no][3] = c1;
    }

    int src0 = (g << 2) | (t >> 1);
    int src1 = src0 + 2;
    bool odd = (t & 1);
    #pragma unroll
    for (int kc2 = 0; kc2 < 8; kc2++) {
        float r0 = acc[kc2][0], r1 = acc[kc2][1];
        float r2 = acc[kc2][2], r3 = acc[kc2][3];
        float x00 = __shfl_sync(0xffffffffu, r0, src0);
        float x01 = __shfl_sync(0xffffffffu, r1, src0);
        float x02 = __shfl_sync(0xffffffffu, r2, src0);
        float x03 = __shfl_sync(0xffffffffu, r3, src0);
        float x10 = __shfl_sync(0xffffffffu, r0, src1);
        float x11 = __shfl_sync(0xffffffffu, r1, src1);
        float x12 = __shfl_sync(0xffffffffu, r2, src1);
        float x13 = __shfl_sync(0xffffffffu, r3, src1);
        unsigned pa[4];
        pa[0] = __float_as_uint(odd ? x01 : x00);
        pa[1] = __float_as_uint(odd ? x03 : x02);
        pa[2] = __float_as_uint(odd ? x11 : x10);
        pa[3] = __float_as_uint(odd ? x13 : x12);
        unsigned bv[2][2];
        #pragma unroll
        for (int no = 0; no < 2; no++) {
            bv[no][0] = svd[(no*8+g)*TS + kc2*8 + t];
            bv[no][1] = svd[(no*8+g)*TS + kc2*8 + t + 4];
        }
        mma8(av[0], pa, bv[0]);
        mma8(av[1], pa, bv[1]);
    }

    float* op = g_o + wbase;
    int q0 = mt*16 + g;
    #pragma unroll
    for (int no = 0; no < 2; no++) {
        int d0 = no*8 + 2*t;
        op[(d0  )*64 + q0    ] = av[no][0];
        op[(d0+1)*64 + q0    ] = av[no][1];
        op[(d0  )*64 + q0 + 8] = av[no][2];
        op[(d0+1)*64 + q0 + 8] = av[no][3];
    }
}

// ---------------- FUSED pools + pad_out + depthwise (window-major o in) ------
__global__ void __launch_bounds__(256) pooldw_kernel(const float* __restrict__ dw)
{
    __shared__ float so[47][48];
    __shared__ float st[39][41];
    __shared__ float sdw[64];
    int bc = blockIdx.z;                       // b*256 + c
    int b = bc >> 8, c = bc & 255;
    int y0 = blockIdx.y*32, x0 = blockIdx.x*32;
    const float* ob = g_o + ((size_t)(b*16 + (c>>4)) << 20) + (size_t)(c & 15)*64;
    int tid = threadIdx.x;
    if (tid < 64) sdw[tid] = dw[c*64 + tid];

    for (int idx = tid; idx < 47*47; idx += 256) {
        int r = idx / 47, cl = idx - r*47;
        int gy = y0 - 6 + r, gx = x0 - 6 + cl;
        float v = 0.f;
        if (gy >= 0 && gy <= 256 && gx >= 0 && gx <= 256) {
            int yy = (gy == 256) ? 254 : gy;
            int xx = (gx == 256) ? 254 : gx;
            v = ob[((size_t)((yy>>3)*32 + (xx>>3)))*1024 + (yy&7)*8 + (xx&7)];
        }
        so[r][cl] = v;
    }
    __syncthreads();

    for (int idx = tid; idx < 39*39; idx += 256) {
        int r = idx / 39, cl = idx - r*39;
        int ty = y0 - 3 + r, tx = x0 - 3 + cl;
        float v = 0.f;
        if (ty >= 0 && ty < 256 && tx >= 0 && tx < 256) {
            float sx = 0.f, sy = 0.f;
            #pragma unroll
            for (int d2 = 0; d2 < 8; d2++) {
                sx += so[r + d2][cl + 3];
                sy += so[r + 3][cl + d2];
            }
            v = (sx + sy)*0.125f;
        }
        st[r][cl] = v;
    }
    __syncthreads();

    int oy = tid >> 3, ox = (tid & 7)*4;
    float a0 = 0.f, a1 = 0.f, a2 = 0.f, a3 = 0.f;
    #pragma unroll
    for (int ky = 0; ky < 8; ky++) {
        const float* row = &st[oy+ky][ox];
        #pragma unroll
        for (int kx = 0; kx < 8; kx++) {
            float wv = sdw[ky*8 + kx];
            a0 += wv*row[kx];
            a1 += wv*row[kx+1];
            a2 += wv*row[kx+2];
            a3 += wv*row[kx+3];
        }
    }
    float* up = g_u + (size_t)bc*HW + (size_t)(y0+oy)*WIMG + x0 + ox;
    *(float4*)up = make_float4(a0,a1,a2,a3);
}

// ---------------- launch ----------------
extern "C" void kernel_launch(void* const* d_in, const int* in_sizes, int n_in,
                              void* d_out, int out_size)
{
    const float* x1       = (const float*)d_in[0];
    const float* x2       = (const float*)d_in[1];
    const float* qkv_w    = (const float*)d_in[2];
    const float* rel_bias = (const float*)d_in[3];
    const float* dw_w     = (const float*)d_in[4];
    const float* bn_g     = (const float*)d_in[5];
    const float* bn_b     = (const float*)d_in[6];
    const float* bn_m     = (const float*)d_in[7];
    const float* bn_v     = (const float*)d_in[8];
    const float* pw_w     = (const float*)d_in[9];
    float* out = (float*)d_out;

    prep_kernel<<<256, 256>>>(pw_w, bn_g, bn_b, bn_m, bn_v);
    bias_prep<<<dim3(NHH, 4, 8), 32>>>(rel_bias);
    xsum_kernel<<<dim3(32, CC, BB), 256>>>(x2);
    vs_gemm<<<dim3(64, BB), 256>>>(qkv_w);
    qkv_gemm<<<dim3(512, 6, BB), 256>>>(x1, x2, qkv_w);
    attn_kernel<<<dim3(2048, NHH), 128>>>();
    pooldw_kernel<<<dim3(8, 8, BB*CC), 256>>>(dw_w);
    pw_gemm<<<dim3(512, 2, BB), 256>>>(out);
}

// round 14
// speedup vs baseline: 1.9837x; 1.0623x over previous
#include <cuda_runtime.h>
#include <cuda_fp16.h>
#include <math.h>

// Problem constants (fixed by setup_inputs)
#define HW    65536          // 256*256
#define WIMG  256
#define CC    256
#define BB    2
#define NHH   16
#define DHH   16

#define QSCALE 0.3606737602222409f    // 0.25 * log2(e)
#define LOG2E  1.4426950408889634f

// ---------------- scratch (device globals; no allocs allowed) ----------------
// q/k/vd/o: WINDOW-major: arr[(b*16+h)*1048576 + w*1024 + d*64 + tok]
static __device__ float g_q [BB*CC*HW];
static __device__ float g_k [BB*CC*HW];
static __device__ float g_vd[BB*CC*HW];            // W_v (x1 - x2)
static __device__ float g_o [BB*CC*HW];
static __device__ float g_u [BB*CC*HW];
static __device__ float g_pwf[CC*CC];
static __device__ float g_pwb[CC];
static __device__ float g_biasf[NHH*4*8*128*4];    // bias in mma C-fragment layout
static __device__ float g_sx [BB*CC*1024];         // per-window sums of x2
static __device__ float g_vs [BB*NHH*1024*16];     // 0.5 * sum_k v2, [bh][w][d]

// ---------------- prep: fold BN into pointwise weights ----------------
__global__ void prep_kernel(const float* __restrict__ pw,
                            const float* __restrict__ gamma,
                            const float* __restrict__ beta,
                            const float* __restrict__ mean,
                            const float* __restrict__ var)
{
    __shared__ float red[256];
    int o = blockIdx.x, c = threadIdx.x;
    float inv = gamma[c] * rsqrtf(var[c] + 1e-5f);
    float w = pw[o*CC + c];
    g_pwf[o*CC + c] = w * inv;
    red[c] = w * (beta[c] - mean[c]*inv);
    __syncthreads();
    for (int s = 128; s > 0; s >>= 1) {
        if (c < s) red[c] += red[c+s];
        __syncthreads();
    }
    if (c == 0) g_pwb[o] = red[0];
}

// ---------------- bias prep: rel-pos bias in mma C-fragment layout, x log2e ----
__global__ void bias_prep(const float* __restrict__ rel_bias)
{
    int h = blockIdx.x, mi = blockIdx.y, ni = blockIdx.z;
    int lane = threadIdx.x;
    int g = lane >> 2, t = lane & 3;
    float v[4];
    #pragma unroll
    for (int rr = 0; rr < 2; rr++) {
        int i = mi*16 + g + rr*8;
        #pragma unroll
        for (int cc = 0; cc < 2; cc++) {
            int j = ni*8 + 2*t + cc;
            int idx = ((i>>3) - (j>>3) + 7)*15 + ((i&7) - (j&7) + 7);
            v[rr*2 + cc] = LOG2E * rel_bias[idx*NHH + h];
        }
    }
    *(float4*)&g_biasf[(((h*4 + mi)*8 + ni)*128 + lane*4)] =
        make_float4(v[0], v[1], v[2], v[3]);
}

// ---------------- window sums of x2 ----------------
__global__ void xsum_kernel(const float* __restrict__ x2)
{
    int tid = threadIdx.x;
    int wy = blockIdx.x, c = blockIdx.y, b = blockIdx.z;
    const float* xp = x2 + ((size_t)(b*CC + c))*HW + (size_t)(wy*8)*WIMG + tid;
    float s = 0.f;
    #pragma unroll
    for (int r = 0; r < 8; r++) s += xp[(size_t)r*WIMG];
    s += __shfl_xor_sync(0xffffffffu, s, 1);
    s += __shfl_xor_sync(0xffffffffu, s, 2);
    s += __shfl_xor_sync(0xffffffffu, s, 4);
    if ((tid & 7) == 0)
        g_sx[((size_t)(b*CC + c))*1024 + wy*32 + (tid >> 3)] = s;
}

// ---------------- tiny GEMM: g_vs = 0.5 * Wv @ g_sx (8 windows/block) --------
__global__ void __launch_bounds__(256) vs_gemm(const float* __restrict__ Wq)
{
    __shared__ float sS[256][9];
    __shared__ float sW[16][257];
    int tid = threadIdx.x;
    int w0 = blockIdx.x * 8, b = blockIdx.y;

    {
        const float* sp = g_sx + ((size_t)(b*CC + tid))*1024 + w0;
        float4 v0 = *(const float4*)(sp);
        float4 v1 = *(const float4*)(sp + 4);
        sS[tid][0]=v0.x; sS[tid][1]=v0.y; sS[tid][2]=v0.z; sS[tid][3]=v0.w;
        sS[tid][4]=v1.x; sS[tid][5]=v1.y; sS[tid][6]=v1.z; sS[tid][7]=v1.w;
    }

    float acc[8];
    #pragma unroll
    for (int j = 0; j < 8; j++) acc[j] = 0.f;

    for (int c0 = 0; c0 < CC; c0 += 16) {
        __syncthreads();
        {
            const float* wp = Wq + (size_t)(512 + tid)*CC + c0;
            float4 w0v = *(const float4*)(wp);
            float4 w1v = *(const float4*)(wp + 4);
            float4 w2v = *(const float4*)(wp + 8);
            float4 w3v = *(const float4*)(wp + 12);
            sW[0][tid]=w0v.x; sW[1][tid]=w0v.y; sW[2][tid]=w0v.z; sW[3][tid]=w0v.w;
            sW[4][tid]=w1v.x; sW[5][tid]=w1v.y; sW[6][tid]=w1v.z; sW[7][tid]=w1v.w;
            sW[8][tid]=w2v.x; sW[9][tid]=w2v.y; sW[10][tid]=w2v.z; sW[11][tid]=w2v.w;
            sW[12][tid]=w3v.x; sW[13][tid]=w3v.y; sW[14][tid]=w3v.z; sW[15][tid]=w3v.w;
        }
        __syncthreads();
        #pragma unroll
        for (int cc = 0; cc < 16; cc++) {
            float wv = sW[cc][tid];
            #pragma unroll
            for (int j = 0; j < 8; j++)
                acc[j] += wv * sS[c0 + cc][j];
        }
    }

    int h = tid >> 4, d = tid & 15;
    #pragma unroll
    for (int j = 0; j < 8; j++)
        g_vs[(((size_t)(b*NHH + h))*1024 + w0 + j)*16 + d] = 0.5f*acc[j];
}

// ---------------- helpers ----------------
__device__ __forceinline__ unsigned f2tf(float x) {
    unsigned r; asm("cvt.rna.tf32.f32 %0, %1;" : "=r"(r) : "f"(x)); return r;
}
__device__ __forceinline__ float ex2(float x) {
    float r; asm("ex2.approx.ftz.f32 %0, %1;" : "=f"(r) : "f"(x)); return r;
}
__device__ __forceinline__ void mma8(float* c, const unsigned* a, const unsigned* b) {
    asm volatile(
        "mma.sync.aligned.m16n8k8.row.col.f32.tf32.tf32.f32 "
        "{%0,%1,%2,%3},{%4,%5,%6,%7},{%8,%9},{%0,%1,%2,%3};"
        : "+f"(c[0]), "+f"(c[1]), "+f"(c[2]), "+f"(c[3])
        : "r"(a[0]), "r"(a[1]), "r"(a[2]), "r"(a[3]), "r"(b[0]), "r"(b[1]));
}
__device__ __forceinline__ void mma16(float* c, const unsigned* a, const unsigned* b) {
    asm volatile(
        "mma.sync.aligned.m16n8k16.row.col.f32.f16.f16.f32 "
        "{%0,%1,%2,%3},{%4,%5,%6,%7},{%8,%9},{%0,%1,%2,%3};"
        : "+f"(c[0]), "+f"(c[1]), "+f"(c[2]), "+f"(c[3])
        : "r"(a[0]), "r"(a[1]), "r"(a[2]), "r"(a[3]), "r"(b[0]), "r"(b[1]));
}
__device__ __forceinline__ unsigned pack_h2(float lo, float hi) {
    __half2 h = __floats2half2_rn(lo, hi);
    return *reinterpret_cast<unsigned*>(&h);
}

// ---------------- core fp16 GEMM tile: 128(M) x 128(N), K=256 ----------------
// 8 warps (4m x 2n), warp tile 32x64, BK=16 (one k16 mma step), double-buffered.
// smem layout: [kpair][m or n] half2 (half2 packs k=2p, 2p+1), stride SA2.
// xb2 != nullptr: B operand is (xb - xb2). wmode=1: window-major store.
#define SA2 136

__device__ __forceinline__ void gemm128_f16(
    const float* __restrict__ wb,
    const float* __restrict__ xb,
    const float* __restrict__ xb2,
    float* __restrict__ ob,
    int n0,
    const float* __restrict__ bias,
    int wmode)
{
    __shared__ __align__(16) unsigned As[2][8*SA2];
    __shared__ __align__(16) unsigned Bs[2][8*SA2];

    int tid  = threadIdx.x;
    int lane = tid & 31, warp = tid >> 5;
    int wm = warp >> 1, wn = warp & 1;
    int gid = lane >> 2, tig = lane & 3;

    float acc[2][8][4];
    #pragma unroll
    for (int mt = 0; mt < 2; mt++)
        #pragma unroll
        for (int nt = 0; nt < 8; nt++)
            #pragma unroll
            for (int i = 0; i < 4; i++) acc[mt][nt][i] = 0.f;

    int arow = tid & 127, akp = (tid >> 7) * 4;   // A: row, kpair base (0 or 4)
    int bkp  = tid >> 5,  bn4 = (tid & 31) * 4;   // B: kpair row, n base

    // prologue: k-block 0 -> buffer 0
    {
        float4 a0 = *(const float4*)(wb + (size_t)arow*CC + akp*2);
        float4 a1 = *(const float4*)(wb + (size_t)arow*CC + akp*2 + 4);
        float4 b0 = *(const float4*)(xb + (size_t)(2*bkp  )*HW + n0 + bn4);
        float4 b1 = *(const float4*)(xb + (size_t)(2*bkp+1)*HW + n0 + bn4);
        if (xb2) {
            float4 c0 = *(const float4*)(xb2 + (size_t)(2*bkp  )*HW + n0 + bn4);
            float4 c1 = *(const float4*)(xb2 + (size_t)(2*bkp+1)*HW + n0 + bn4);
            b0.x -= c0.x; b0.y -= c0.y; b0.z -= c0.z; b0.w -= c0.w;
            b1.x -= c1.x; b1.y -= c1.y; b1.z -= c1.z; b1.w -= c1.w;
        }
        As[0][(akp+0)*SA2 + arow] = pack_h2(a0.x, a0.y);
        As[0][(akp+1)*SA2 + arow] = pack_h2(a0.z, a0.w);
        As[0][(akp+2)*SA2 + arow] = pack_h2(a1.x, a1.y);
        As[0][(akp+3)*SA2 + arow] = pack_h2(a1.z, a1.w);
        *(uint4*)&Bs[0][bkp*SA2 + bn4] =
            make_uint4(pack_h2(b0.x, b1.x), pack_h2(b0.y, b1.y),
                       pack_h2(b0.z, b1.z), pack_h2(b0.w, b1.w));
    }
    __syncthreads();

    #pragma unroll 2
    for (int it = 0; it < 16; it++) {
        int p = it & 1;
        float4 a0, a1, b0, b1;
        if (it < 15) {
            int k0 = (it + 1) * 16;
            a0 = *(const float4*)(wb + (size_t)arow*CC + k0 + akp*2);
            a1 = *(const float4*)(wb + (size_t)arow*CC + k0 + akp*2 + 4);
            b0 = *(const float4*)(xb + (size_t)(k0 + 2*bkp  )*HW + n0 + bn4);
            b1 = *(const float4*)(xb + (size_t)(k0 + 2*bkp+1)*HW + n0 + bn4);
            if (xb2) {
                float4 c0 = *(const float4*)(xb2 + (size_t)(k0 + 2*bkp  )*HW + n0 + bn4);
                float4 c1 = *(const float4*)(xb2 + (size_t)(k0 + 2*bkp+1)*HW + n0 + bn4);
                b0.x -= c0.x; b0.y -= c0.y; b0.z -= c0.z; b0.w -= c0.w;
                b1.x -= c1.x; b1.y -= c1.y; b1.z -= c1.z; b1.w -= c1.w;
            }
        }

        unsigned af[2][4], bf[8][2];
        #pragma unroll
        for (int mt = 0; mt < 2; mt++) {
            int m = wm*32 + mt*16 + gid;
            af[mt][0] = As[p][(tig  )*SA2 + m];
            af[mt][1] = As[p][(tig  )*SA2 + m + 8];
            af[mt][2] = As[p][(tig+4)*SA2 + m];
            af[mt][3] = As[p][(tig+4)*SA2 + m + 8];
        }
        #pragma unroll
        for (int nt = 0; nt < 8; nt++) {
            int n = wn*64 + nt*8 + gid;
            bf[nt][0] = Bs[p][(tig  )*SA2 + n];
            bf[nt][1] = Bs[p][(tig+4)*SA2 + n];
        }
        #pragma unroll
        for (int mt = 0; mt < 2; mt++)
            #pragma unroll
            for (int nt = 0; nt < 8; nt++)
                mma16(acc[mt][nt], af[mt], bf[nt]);

        if (it < 15) {
            int q = p ^ 1;
            As[q][(akp+0)*SA2 + arow] = pack_h2(a0.x, a0.y);
            As[q][(akp+1)*SA2 + arow] = pack_h2(a0.z, a0.w);
            As[q][(akp+2)*SA2 + arow] = pack_h2(a1.x, a1.y);
            As[q][(akp+3)*SA2 + arow] = pack_h2(a1.z, a1.w);
            *(uint4*)&Bs[q][bkp*SA2 + bn4] =
                make_uint4(pack_h2(b0.x, b1.x), pack_h2(b0.y, b1.y),
                           pack_h2(b0.z, b1.z), pack_h2(b0.w, b1.w));
        }
        __syncthreads();
    }

    if (wmode) {
        int y = n0 >> 8, xb0 = n0 & 255;
        int wy = y >> 3, ty = y & 7;
        #pragma unroll
        for (int mt = 0; mt < 2; mt++) {
            int hloc = wm*2 + mt;
            #pragma unroll
            for (int nt = 0; nt < 8; nt++) {
                int x = xb0 + wn*64 + nt*8 + 2*tig;
                size_t a0 = ((size_t)hloc*1024 + wy*32 + (x>>3))*16;
                int tx = ty*8 + (x&7);
                *(float2*)(ob + (a0 + gid    )*64 + tx) =
                    make_float2(acc[mt][nt][0], acc[mt][nt][1]);
                *(float2*)(ob + (a0 + gid + 8)*64 + tx) =
                    make_float2(acc[mt][nt][2], acc[mt][nt][3]);
            }
        }
    } else {
        #pragma unroll
        for (int mt = 0; mt < 2; mt++) {
            int r0 = wm*32 + mt*16 + gid;
            float bia0 = bias ? bias[r0]     : 0.f;
            float bia1 = bias ? bias[r0 + 8] : 0.f;
            #pragma unroll
            for (int nt = 0; nt < 8; nt++) {
                int c = n0 + wn*64 + nt*8 + 2*tig;
                *(float2*)(ob + (size_t)r0*HW + c) =
                    make_float2(acc[mt][nt][0] + bia0, acc[mt][nt][1] + bia0);
                *(float2*)(ob + (size_t)(r0+8)*HW + c) =
                    make_float2(acc[mt][nt][2] + bia1, acc[mt][nt][3] + bia1);
            }
        }
    }
}

// ---------------- qkv GEMM: q from x1, k from x2, vd from (x1-x2) ------------
__global__ void __launch_bounds__(256, 2) qkv_gemm(const float* __restrict__ x1,
                                                   const float* __restrict__ x2,
                                                   const float* __restrict__ Wq)
{
    int b  = blockIdx.z;
    int by = blockIdx.y;
    int n0 = blockIdx.x * 128;
    const float* wb;
    const float* xa;
    const float* xd2 = nullptr;
    float* ob;
    if (by < 2) {
        wb = Wq + (size_t)(by*128)*CC;
        ob = g_q + ((size_t)(b*16 + by*8) << 20);
        xa = x1;
    } else if (by < 4) {
        wb = Wq + (size_t)(256 + (by-2)*128)*CC;
        ob = g_k + ((size_t)(b*16 + (by-2)*8) << 20);
        xa = x2;
    } else {
        wb = Wq + (size_t)(512 + (by-4)*128)*CC;
        ob = g_vd + ((size_t)(b*16 + (by-4)*8) << 20);
        xa = x1; xd2 = x2 + (size_t)b*CC*HW;
    }
    xa += (size_t)b*CC*HW;
    gemm128_f16(wb, xa, xd2, ob, n0, nullptr, 1);
}

// ---------------- pointwise GEMM (BN folded, fp16, image layout) -------------
__global__ void __launch_bounds__(256, 2) pw_gemm(float* __restrict__ out)
{
    int b  = blockIdx.z;
    int by = blockIdx.y;
    int n0 = blockIdx.x * 128;
    const float* wb = g_pwf + (size_t)(by*128)*CC;
    const float* xb = g_u + (size_t)b*CC*HW;
    float* ob = out + (size_t)b*CC*HW + (size_t)(by*128)*HW;
    gemm128_f16(wb, xb, nullptr, ob, n0, g_pwb + by*128, 0);
}

// ---------------- window attention: tensor-core (mma tf32) ----------------
// o = softmax(q k^T*0.25 + bias) @ (0.5*(v1-v2)) + 0.5*sum_k v2
#define TS 72

__global__ void __launch_bounds__(128, 5) attn_kernel()
{
    int wid = blockIdx.x;                 // 0..2047
    int h   = blockIdx.y;                 // 0..15
    int b   = wid >> 10;
    int w   = wid & 1023;
    int tid = threadIdx.x;
    int lane = tid & 31;
    int mt   = tid >> 5;                  // m-tile 0..3 (16 queries each)
    int g = lane >> 2, t = lane & 3;

    __shared__ unsigned sq [16*TS];       // tf32(q * 0.25*log2e)
    __shared__ unsigned sk [16*TS];       // tf32(k)
    __shared__ unsigned svd[16*TS];       // tf32(0.5*vd)
    __shared__ float svs[16];             // 0.5*sum_k v2

    size_t wbase = ((size_t)((b*NHH + h)*1024 + w)) * 1024;

    if (tid < 16) svs[tid] = g_vs[((size_t)((b*NHH + h)*1024 + w))*16 + tid];

    {
        int j = tid & 7, dd = tid >> 3;
        int t0 = j*8;
        size_t off = wbase + dd*64 + t0;
        float4 qa = *(const float4*)(g_q + off), qb2 = *(const float4*)(g_q + off + 4);
        float4 ka = *(const float4*)(g_k + off), kb2 = *(const float4*)(g_k + off + 4);
        float4 va = *(const float4*)(g_vd + off), vb2 = *(const float4*)(g_vd + off + 4);
        unsigned* sp = &sq[dd*TS + t0];
        sp[0]=f2tf(qa.x*QSCALE); sp[1]=f2tf(qa.y*QSCALE); sp[2]=f2tf(qa.z*QSCALE); sp[3]=f2tf(qa.w*QSCALE);
        sp[4]=f2tf(qb2.x*QSCALE); sp[5]=f2tf(qb2.y*QSCALE); sp[6]=f2tf(qb2.z*QSCALE); sp[7]=f2tf(qb2.w*QSCALE);
        sp = &sk[dd*TS + t0];
        sp[0]=f2tf(ka.x); sp[1]=f2tf(ka.y); sp[2]=f2tf(ka.z); sp[3]=f2tf(ka.w);
        sp[4]=f2tf(kb2.x); sp[5]=f2tf(kb2.y); sp[6]=f2tf(kb2.z); sp[7]=f2tf(kb2.w);
        sp = &svd[dd*TS + t0];
        sp[0]=f2tf(0.5f*va.x); sp[1]=f2tf(0.5f*va.y); sp[2]=f2tf(0.5f*va.z); sp[3]=f2tf(0.5f*va.w);
        sp[4]=f2tf(0.5f*vb2.x); sp[5]=f2tf(0.5f*vb2.y); sp[6]=f2tf(0.5f*vb2.z); sp[7]=f2tf(0.5f*vb2.w);
    }
    __syncthreads();

    int r0q = mt*16 + g;
    unsigned aq[2][4];
    #pragma unroll
    for (int kc = 0; kc < 2; kc++) {
        aq[kc][0] = sq[(kc*8+t  )*TS + r0q];
        aq[kc][1] = sq[(kc*8+t  )*TS + r0q + 8];
        aq[kc][2] = sq[(kc*8+t+4)*TS + r0q];
        aq[kc][3] = sq[(kc*8+t+4)*TS + r0q + 8];
    }

    float acc[8][4];
    #pragma unroll
    for (int ni = 0; ni < 8; ni++) {
        float4 bv = *(const float4*)&g_biasf[(((h*4 + mt)*8 + ni)*128 + lane*4)];
        acc[ni][0] = bv.x; acc[ni][1] = bv.y;
        acc[ni][2] = bv.z; acc[ni][3] = bv.w;
    }

    #pragma unroll
    for (int ni = 0; ni < 8; ni++) {
        unsigned bk[2][2];
        #pragma unroll
        for (int kc = 0; kc < 2; kc++) {
            bk[kc][0] = sk[(kc*8+t  )*TS + ni*8 + g];
            bk[kc][1] = sk[(kc*8+t+4)*TS + ni*8 + g];
        }
        mma8(acc[ni], aq[0], bk[0]);
        mma8(acc[ni], aq[1], bk[1]);
    }

    {
        float m0 = -1e30f, m1 = -1e30f;
        #pragma unroll
        for (int ni = 0; ni < 8; ni++) {
            m0 = fmaxf(m0, fmaxf(acc[ni][0], acc[ni][1]));
            m1 = fmaxf(m1, fmaxf(acc[ni][2], acc[ni][3]));
        }
        m0 = fmaxf(m0, __shfl_xor_sync(0xffffffffu, m0, 1));
        m0 = fmaxf(m0, __shfl_xor_sync(0xffffffffu, m0, 2));
        m1 = fmaxf(m1, __shfl_xor_sync(0xffffffffu, m1, 1));
        m1 = fmaxf(m1, __shfl_xor_sync(0xffffffffu, m1, 2));
        float s0 = 0.f, s1 = 0.f;
        #pragma unroll
        for (int ni = 0; ni < 8; ni++) {
            float p0 = ex2(acc[ni][0] - m0);
            float p1 = ex2(acc[ni][1] - m0);
            float p2 = ex2(acc[ni][2] - m1);
            float p3 = ex2(acc[ni][3] - m1);
            acc[ni][0] = p0; acc[ni][1] = p1;
            acc[ni][2] = p2; acc[ni][3] = p3;
            s0 += p0 + p1; s1 += p2 + p3;
        }
        s0 += __shfl_xor_sync(0xffffffffu, s0, 1);
        s0 += __shfl_xor_sync(0xffffffffu, s0, 2);
        s1 += __shfl_xor_sync(0xffffffffu, s1, 1);
        s1 += __shfl_xor_sync(0xffffffffu, s1, 2);
        float i0 = 1.0f / s0, i1 = 1.0f / s1;
        #pragma unroll
        for (int ni = 0; ni < 8; ni++) {
            acc[ni][0] = __uint_as_float(f2tf(acc[ni][0]*i0));
            acc[ni][1] = __uint_as_float(f2tf(acc[ni][1]*i0));
            acc[ni][2] = __uint_as_float(f2tf(acc[ni][2]*i1));
            acc[ni][3] = __uint_as_float(f2tf(acc[ni][3]*i1));
        }
    }

    float av[2][4];
    #pragma unroll
    for (int no = 0; no < 2; no++) {
        float c0 = svs[no*8 + 2*t];
        float c1 = svs[no*8 + 2*t + 1];
        av[no][0] = c0; av[no][1] = c1;
        av[no][2] = c0; av[no][3] = c1;
    }

    int src0 = (g << 2) | (t >> 1);
    int src1 = src0 + 2;
    bool odd = (t & 1);
    #pragma unroll
    for (int kc2 = 0; kc2 < 8; kc2++) {
        float r0 = acc[kc2][0], r1 = acc[kc2][1];
        float r2 = acc[kc2][2], r3 = acc[kc2][3];
        float x00 = __shfl_sync(0xffffffffu, r0, src0);
        float x01 = __shfl_sync(0xffffffffu, r1, src0);
        float x02 = __shfl_sync(0xffffffffu, r2, src0);
        float x03 = __shfl_sync(0xffffffffu, r3, src0);
        float x10 = __shfl_sync(0xffffffffu, r0, src1);
        float x11 = __shfl_sync(0xffffffffu, r1, src1);
        float x12 = __shfl_sync(0xffffffffu, r2, src1);
        float x13 = __shfl_sync(0xffffffffu, r3, src1);
        unsigned pa[4];
        pa[0] = __float_as_uint(odd ? x01 : x00);
        pa[1] = __float_as_uint(odd ? x03 : x02);
        pa[2] = __float_as_uint(odd ? x11 : x10);
        pa[3] = __float_as_uint(odd ? x13 : x12);
        unsigned bv[2][2];
        #pragma unroll
        for (int no = 0; no < 2; no++) {
            bv[no][0] = svd[(no*8+g)*TS + kc2*8 + t];
            bv[no][1] = svd[(no*8+g)*TS + kc2*8 + t + 4];
        }
        mma8(av[0], pa, bv[0]);
        mma8(av[1], pa, bv[1]);
    }

    float* op = g_o + wbase;
    int q0 = mt*16 + g;
    #pragma unroll
    for (int no = 0; no < 2; no++) {
        int d0 = no*8 + 2*t;
        op[(d0  )*64 + q0    ] = av[no][0];
        op[(d0+1)*64 + q0    ] = av[no][1];
        op[(d0  )*64 + q0 + 8] = av[no][2];
        op[(d0+1)*64 + q0 + 8] = av[no][3];
    }
}

// ---------------- FUSED pools + pad_out + depthwise (window-major o in) ------
__global__ void __launch_bounds__(256) pooldw_kernel(const float* __restrict__ dw)
{
    __shared__ float so[47][48];
    __shared__ float st[39][41];
    __shared__ float sdw[64];
    int bc = blockIdx.z;                       // b*256 + c
    int b = bc >> 8, c = bc & 255;
    int y0 = blockIdx.y*32, x0 = blockIdx.x*32;
    const float* ob = g_o + ((size_t)(b*16 + (c>>4)) << 20) + (size_t)(c & 15)*64;
    int tid = threadIdx.x;
    if (tid < 64) sdw[tid] = dw[c*64 + tid];

    for (int idx = tid; idx < 47*47; idx += 256) {
        int r = idx / 47, cl = idx - r*47;
        int gy = y0 - 6 + r, gx = x0 - 6 + cl;
        float v = 0.f;
        if (gy >= 0 && gy <= 256 && gx >= 0 && gx <= 256) {
            int yy = (gy == 256) ? 254 : gy;
            int xx = (gx == 256) ? 254 : gx;
            v = ob[((size_t)((yy>>3)*32 + (xx>>3)))*1024 + (yy&7)*8 + (xx&7)];
        }
        so[r][cl] = v;
    }
    __syncthreads();

    for (int idx = tid; idx < 39*39; idx += 256) {
        int r = idx / 39, cl = idx - r*39;
        int ty = y0 - 3 + r, tx = x0 - 3 + cl;
        float v = 0.f;
        if (ty >= 0 && ty < 256 && tx >= 0 && tx < 256) {
            float sx = 0.f, sy = 0.f;
            #pragma unroll
            for (int d2 = 0; d2 < 8; d2++) {
                sx += so[r + d2][cl + 3];
                sy += so[r + 3][cl + d2];
            }
            v = (sx + sy)*0.125f;
        }
        st[r][cl] = v;
    }
    __syncthreads();

    int oy = tid >> 3, ox = (tid & 7)*4;
    float a0 = 0.f, a1 = 0.f, a2 = 0.f, a3 = 0.f;
    #pragma unroll
    for (int ky = 0; ky < 8; ky++) {
        const float* row = &st[oy+ky][ox];
        #pragma unroll
        for (int kx = 0; kx < 8; kx++) {
            float wv = sdw[ky*8 + kx];
            a0 += wv*row[kx];
            a1 += wv*row[kx+1];
            a2 += wv*row[kx+2];
            a3 += wv*row[kx+3];
        }
    }
    float* up = g_u + (size_t)bc*HW + (size_t)(y0+oy)*WIMG + x0 + ox;
    *(float4*)up = make_float4(a0,a1,a2,a3);
}

// ---------------- launch ----------------
extern "C" void kernel_launch(void* const* d_in, const int* in_sizes, int n_in,
                              void* d_out, int out_size)
{
    const float* x1       = (const float*)d_in[0];
    const float* x2       = (const float*)d_in[1];
    const float* qkv_w    = (const float*)d_in[2];
    const float* rel_bias = (const float*)d_in[3];
    const float* dw_w     = (const float*)d_in[4];
    const float* bn_g     = (const float*)d_in[5];
    const float* bn_b     = (const float*)d_in[6];
    const float* bn_m     = (const float*)d_in[7];
    const float* bn_v     = (const float*)d_in[8];
    const float* pw_w     = (const float*)d_in[9];
    float* out = (float*)d_out;

    prep_kernel<<<256, 256>>>(pw_w, bn_g, bn_b, bn_m, bn_v);
    bias_prep<<<dim3(NHH, 4, 8), 32>>>(rel_bias);
    xsum_kernel<<<dim3(32, CC, BB), 256>>>(x2);
    vs_gemm<<<dim3(128, BB), 256>>>(qkv_w);
    qkv_gemm<<<dim3(512, 6, BB), 256>>>(x1, x2, qkv_w);
    attn_kernel<<<dim3(2048, NHH), 128>>>();
    pooldw_kernel<<<dim3(8, 8, BB*CC), 256>>>(dw_w);
    pw_gemm<<<dim3(512, 2, BB), 256>>>(out);
}